// round 3
// baseline (speedup 1.0000x reference)
#include <cuda_runtime.h>

#define CCH    192
#define LG     3
#define HWSZ   16384
#define PIX    128
#define NTHR   192
#define KCH    32
#define NCHUNK 6
#define EPSV   1e-6f

typedef unsigned long long u64;

__device__ __forceinline__ u64 pack2(float a, float b) {
    u64 r; asm("mov.b64 %0, {%1, %2};" : "=l"(r) : "f"(a), "f"(b)); return r;
}
__device__ __forceinline__ void fma2(u64& d, u64 a, u64 b) {
    asm("fma.rn.f32x2 %0, %1, %2, %0;" : "+l"(d) : "l"(a), "l"(b));
}
__device__ __forceinline__ u64 mul2(u64 a, u64 b) {
    u64 r; asm("mul.rn.f32x2 %0, %1, %2;" : "=l"(r) : "l"(a), "l"(b)); return r;
}

// smem layout (floats)
#define OFF_XS 0         // x tile [c][pos]           24576
#define OFF_CT 24576     // ctx/mod/t/y [c][pos]      24576
#define OFF_WA 49152     // weight chunk [o][32] swz   6144
#define OFF_GS 55296     // gates [l][pos]              384
#define OFF_MU 55680     // per-pos mean                128
#define OFF_RS 55808     // per-pos rstd                128
#define SMEM_FLOATS 55936

// pos chunk L (0..31) <-> global pixel quad g
__device__ __forceinline__ int gquad(int L) { return ((L & 7) << 2) | (L >> 3); }

__device__ __forceinline__ void stage_weights(const float* __restrict__ Wg,
                                              float* wA, int k0, int t) {
    #pragma unroll
    for (int j = 0; j < 8; ++j) {
        int f4 = t + j * NTHR;
        int o = f4 >> 3, kq = f4 & 7;
        float4 v = *reinterpret_cast<const float4*>(Wg + (size_t)o * CCH + k0 + 4 * kq);
        int swz = kq ^ (o & 7) ^ ((o >> 3) & 7);
        *reinterpret_cast<float4*>(wA + o * KCH + 4 * swz) = v;
    }
}

// one matvec pass: acc[c*8 + 2*mq + s] over 8 channels (8*og+c) x 16 pixels
__device__ __forceinline__ void mv_pass(const float* __restrict__ Wg,
                                        const float* __restrict__ data,
                                        float* wA, u64 (&acc)[64],
                                        int og, int pg, int t) {
    const int ogx = og & 7;
    #pragma unroll 1
    for (int ch = 0; ch < NCHUNK; ++ch) {
        const int k0 = ch * KCH;
        stage_weights(Wg, wA, k0, t);
        __syncthreads();
        #pragma unroll 1
        for (int m = 0; m < 8; ++m) {
            float4 wq[8];
            #pragma unroll
            for (int c = 0; c < 8; ++c) {
                int row = 8 * og + c;
                int swz = m ^ c ^ ogx;
                wq[c] = *reinterpret_cast<const float4*>(wA + row * KCH + 4 * swz);
            }
            const float* drb = data + (k0 + 4 * m) * PIX + 4 * pg;
            #pragma unroll
            for (int kk = 0; kk < 4; ++kk) {
                const float* dr = drb + kk * PIX;
                ulonglong2 d0 = *reinterpret_cast<const ulonglong2*>(dr);
                ulonglong2 d1 = *reinterpret_cast<const ulonglong2*>(dr + 32);
                ulonglong2 d2 = *reinterpret_cast<const ulonglong2*>(dr + 64);
                ulonglong2 d3 = *reinterpret_cast<const ulonglong2*>(dr + 96);
                #pragma unroll
                for (int c = 0; c < 8; ++c) {
                    float w = (kk == 0) ? wq[c].x : (kk == 1) ? wq[c].y
                            : (kk == 2) ? wq[c].z : wq[c].w;
                    u64 w2 = pack2(w, w);
                    fma2(acc[c*8+0], d0.x, w2); fma2(acc[c*8+1], d0.y, w2);
                    fma2(acc[c*8+2], d1.x, w2); fma2(acc[c*8+3], d1.y, w2);
                    fma2(acc[c*8+4], d2.x, w2); fma2(acc[c*8+5], d2.y, w2);
                    fma2(acc[c*8+6], d3.x, w2); fma2(acc[c*8+7], d3.y, w2);
                }
            }
        }
        __syncthreads();
    }
}

__device__ __forceinline__ void init_acc(u64 (&acc)[64], const float* __restrict__ bias, int og) {
    float4 b0 = *reinterpret_cast<const float4*>(bias + 8 * og);
    float4 b1 = *reinterpret_cast<const float4*>(bias + 8 * og + 4);
    float bb[8] = {b0.x, b0.y, b0.z, b0.w, b1.x, b1.y, b1.z, b1.w};
    #pragma unroll
    for (int c = 0; c < 8; ++c) {
        u64 v = pack2(bb[c], bb[c]);
        #pragma unroll
        for (int i = 0; i < 8; ++i) acc[c * 8 + i] = v;
    }
}

__global__ void __launch_bounds__(NTHR, 1)
CM_29540785062535_kernel(const float* __restrict__ x,
                         const float* __restrict__ xl,
                         const float* __restrict__ fw,
                         const float* __restrict__ fb,
                         const float* __restrict__ hwm,
                         const float* __restrict__ hb,
                         const float* __restrict__ pw,
                         const float* __restrict__ pb,
                         const float* __restrict__ lnw,
                         const float* __restrict__ lnb,
                         float* __restrict__ out,
                         int Nn)
{
    extern __shared__ float sm[];
    float* xs   = sm + OFF_XS;
    float* ctxs = sm + OFF_CT;
    float* wA   = sm + OFF_WA;
    float* gs   = sm + OFF_GS;
    float* mus  = sm + OFF_MU;
    float* rss  = sm + OFF_RS;

    const int t  = threadIdx.x;
    const int og = t >> 3;        // 0..23 : channels 8*og..8*og+7
    const int pg = t & 7;         // 0..7  : pixel groups
    const int b  = blockIdx.x;
    const int n  = b >> 7;        // 128 row-tiles per image
    const int hw0 = (b & 127) << 7;

    // ---- stage x tile into pos layout ----
    {
        const float* xb = x + ((size_t)n * CCH) * HWSZ + hw0;
        #pragma unroll 4
        for (int u = 0; u < 32; ++u) {
            int f4 = t + u * NTHR;
            int c = f4 >> 5, L = f4 & 31;
            float4 v = *reinterpret_cast<const float4*>(xb + (size_t)c * HWSZ + 4 * gquad(L));
            *reinterpret_cast<float4*>(xs + c * PIX + 4 * L) = v;
        }
    }
    __syncthreads();

    // ---- gates: 2 slots per thread ----
    {
        int s1 = t, s2 = t + NTHR;
        int l1 = s1 >> 7, p1 = s1 & 127;
        int l2 = s2 >> 7, p2 = s2 & 127;
        const float* w1 = fw + (size_t)(CCH + l1) * CCH;
        const float* w2 = fw + (size_t)(CCH + l2) * CCH;
        float a0 = 0.f, a1 = 0.f, b0 = 0.f, b1 = 0.f;
        #pragma unroll 4
        for (int k = 0; k < CCH; k += 4) {
            float4 wv1 = *reinterpret_cast<const float4*>(w1 + k);
            float4 wv2 = *reinterpret_cast<const float4*>(w2 + k);
            a0 = fmaf(wv1.x, xs[(k+0)*PIX + p1], a0);
            a1 = fmaf(wv1.y, xs[(k+1)*PIX + p1], a1);
            a0 = fmaf(wv1.z, xs[(k+2)*PIX + p1], a0);
            a1 = fmaf(wv1.w, xs[(k+3)*PIX + p1], a1);
            b0 = fmaf(wv2.x, xs[(k+0)*PIX + p2], b0);
            b1 = fmaf(wv2.y, xs[(k+1)*PIX + p2], b1);
            b0 = fmaf(wv2.z, xs[(k+2)*PIX + p2], b0);
            b1 = fmaf(wv2.w, xs[(k+3)*PIX + p2], b1);
        }
        gs[s1] = a0 + a1 + fb[CCH + l1];
        gs[s2] = b0 + b1 + fb[CCH + l2];
    }
    __syncthreads();

    // ---- ctx = sum_l gates[l] * x_list[l] (streamed), into pos layout ----
    #pragma unroll 1
    for (int jj = 0; jj < 4; ++jj) {
        float4 ca[8];
        #pragma unroll
        for (int l = 0; l < LG; ++l) {
            const float* src = xl + ((size_t)(l * Nn + n) * CCH) * HWSZ + hw0;
            #pragma unroll
            for (int j = 0; j < 8; ++j) {
                int f4 = t + (jj * 8 + j) * NTHR;
                int c = f4 >> 5, L = f4 & 31;
                float4 v = *reinterpret_cast<const float4*>(src + (size_t)c * HWSZ + 4 * gquad(L));
                float4 g4 = *reinterpret_cast<const float4*>(gs + l * PIX + 4 * L);
                if (l == 0) {
                    ca[j].x = g4.x * v.x; ca[j].y = g4.y * v.y;
                    ca[j].z = g4.z * v.z; ca[j].w = g4.w * v.w;
                } else {
                    ca[j].x = fmaf(g4.x, v.x, ca[j].x);
                    ca[j].y = fmaf(g4.y, v.y, ca[j].y);
                    ca[j].z = fmaf(g4.z, v.z, ca[j].z);
                    ca[j].w = fmaf(g4.w, v.w, ca[j].w);
                }
            }
        }
        #pragma unroll
        for (int j = 0; j < 8; ++j) {
            int f4 = t + (jj * 8 + j) * NTHR;
            int c = f4 >> 5, L = f4 & 31;
            *reinterpret_cast<float4*>(ctxs + c * PIX + 4 * L) = ca[j];
        }
    }
    __syncthreads();

    u64 acc[64];

    // ---- pass 1: mod = hw @ ctx ----
    init_acc(acc, hb, og);
    mv_pass(hwm, ctxs, wA, acc, og, pg, t);
    // store mod into ctxs (ctx fully consumed)
    #pragma unroll
    for (int c = 0; c < 8; ++c)
        #pragma unroll
        for (int mq = 0; mq < 4; ++mq) {
            ulonglong2 v; v.x = acc[c*8+2*mq]; v.y = acc[c*8+2*mq+1];
            *reinterpret_cast<ulonglong2*>(ctxs + (8*og+c)*PIX + 32*mq + 4*pg) = v;
        }
    __syncthreads();

    // ---- pass 2: q = fw[:C] @ x ; t = q * mod ----
    init_acc(acc, fb, og);
    mv_pass(fw, xs, wA, acc, og, pg, t);
    #pragma unroll
    for (int c = 0; c < 8; ++c)
        #pragma unroll
        for (int mq = 0; mq < 4; ++mq) {
            float* p = ctxs + (8*og+c)*PIX + 32*mq + 4*pg;
            ulonglong2 md = *reinterpret_cast<const ulonglong2*>(p);
            md.x = mul2(acc[c*8+2*mq],   md.x);
            md.y = mul2(acc[c*8+2*mq+1], md.y);
            *reinterpret_cast<ulonglong2*>(p) = md;
        }
    __syncthreads();

    // ---- pass 3: y = pw @ t ----
    init_acc(acc, pb, og);
    mv_pass(pw, ctxs, wA, acc, og, pg, t);
    // store y into ctxs (t fully consumed)
    #pragma unroll
    for (int c = 0; c < 8; ++c)
        #pragma unroll
        for (int mq = 0; mq < 4; ++mq) {
            ulonglong2 v; v.x = acc[c*8+2*mq]; v.y = acc[c*8+2*mq+1];
            *reinterpret_cast<ulonglong2*>(ctxs + (8*og+c)*PIX + 32*mq + 4*pg) = v;
        }
    __syncthreads();

    // ---- LN stats: one pos-pixel per thread (t < 128) ----
    if (t < PIX) {
        float s0 = 0.f, s1 = 0.f, q0 = 0.f, q1 = 0.f;
        #pragma unroll 2
        for (int c = 0; c < CCH; c += 4) {
            float v0 = ctxs[(c+0)*PIX + t];
            float v1 = ctxs[(c+1)*PIX + t];
            float v2 = ctxs[(c+2)*PIX + t];
            float v3 = ctxs[(c+3)*PIX + t];
            s0 += v0 + v1;  s1 += v2 + v3;
            q0 = fmaf(v0, v0, q0); q1 = fmaf(v1, v1, q1);
            q0 = fmaf(v2, v2, q0); q1 = fmaf(v3, v3, q1);
        }
        float mu  = (s0 + s1) * (1.0f / CCH);
        float var = (q0 + q1) * (1.0f / CCH) - mu * mu;
        mus[t] = mu;
        rss[t] = rsqrtf(var + EPSV);
    }
    __syncthreads();

    // ---- normalize + residual + store (pos -> global quad) ----
    {
        float* ob = out + ((size_t)n * CCH) * HWSZ + hw0;
        #pragma unroll 4
        for (int u = 0; u < 32; ++u) {
            int f4 = t + u * NTHR;
            int c = f4 >> 5, L = f4 & 31;
            float4 y4 = *reinterpret_cast<const float4*>(ctxs + c * PIX + 4 * L);
            float4 x4 = *reinterpret_cast<const float4*>(xs   + c * PIX + 4 * L);
            float4 m4 = *reinterpret_cast<const float4*>(mus + 4 * L);
            float4 r4 = *reinterpret_cast<const float4*>(rss + 4 * L);
            float lw = lnw[c], lb = lnb[c];
            float4 r;
            r.x = fmaf(lw * (y4.x - m4.x), r4.x, lb) + x4.x;
            r.y = fmaf(lw * (y4.y - m4.y), r4.y, lb) + x4.y;
            r.z = fmaf(lw * (y4.z - m4.z), r4.z, lb) + x4.z;
            r.w = fmaf(lw * (y4.w - m4.w), r4.w, lb) + x4.w;
            *reinterpret_cast<float4*>(ob + (size_t)c * HWSZ + 4 * gquad(L)) = r;
        }
    }
}

extern "C" void kernel_launch(void* const* d_in, const int* in_sizes, int n_in,
                              void* d_out, int out_size) {
    const float* x   = (const float*)d_in[0];
    const float* xl  = (const float*)d_in[1];
    const float* fw  = (const float*)d_in[2];
    const float* fb  = (const float*)d_in[3];
    const float* hwm = (const float*)d_in[4];
    const float* hb  = (const float*)d_in[5];
    const float* pw  = (const float*)d_in[6];
    const float* pb  = (const float*)d_in[7];
    const float* lnw = (const float*)d_in[8];
    const float* lnb = (const float*)d_in[9];
    float* out = (float*)d_out;

    int Nn = in_sizes[0] / (CCH * HWSZ);
    size_t smem = SMEM_FLOATS * sizeof(float);   // 223744 B

    cudaFuncSetAttribute(CM_29540785062535_kernel,
                         cudaFuncAttributeMaxDynamicSharedMemorySize, (int)smem);

    int blocks = Nn * (HWSZ / PIX);   // 16 * 128 = 2048
    CM_29540785062535_kernel<<<blocks, NTHR, smem>>>(
        x, xl, fw, fb, hwm, hb, pw, pb, lnw, lnb, out, Nn);
}

// round 4
// speedup vs baseline: 1.2689x; 1.2689x over previous
#include <cuda_runtime.h>

#define CCH    192
#define LG     3
#define HWSZ   16384
#define PIX    64
#define NTHR   192
#define KCH    16
#define NCHUNK 12
#define EPSV   1e-6f

typedef unsigned long long u64;

__device__ __forceinline__ u64 pack2(float a, float b) {
    u64 r; asm("mov.b64 %0, {%1, %2};" : "=l"(r) : "f"(a), "f"(b)); return r;
}
__device__ __forceinline__ void fma2(u64& d, u64 a, u64 b) {
    asm("fma.rn.f32x2 %0, %1, %2, %0;" : "+l"(d) : "l"(a), "l"(b));
}
__device__ __forceinline__ u64 mul2(u64 a, u64 b) {
    u64 r; asm("mul.rn.f32x2 %0, %1, %2;" : "=l"(r) : "l"(a), "l"(b)); return r;
}

// smem layout (floats)
#define OFF_XS 0         // x tile [c][pos]        12288
#define OFF_CT 12288     // ctx/mod/t/y [c][pos]   12288
#define OFF_WA 24576     // weight chunk [o][16]    3072 (reused for LN partials)
#define OFF_GS 27648     // gates [l][pos]           192
#define OFF_MU 27840     // per-pos mean              64
#define OFF_RS 27904     // per-pos rstd              64
#define SMEM_FLOATS 27968   // 111872 B -> 2 blocks/SM

__device__ __forceinline__ void stage_weights(const float* __restrict__ Wg,
                                              float* wA, int k0, int t) {
    #pragma unroll
    for (int j = 0; j < 4; ++j) {
        int f4 = t + j * NTHR;
        int o = f4 >> 2, kq = f4 & 3;
        float4 v = *reinterpret_cast<const float4*>(Wg + (size_t)o * CCH + k0 + 4 * kq);
        int col = (kq + o + (o >> 3)) & 3;
        *reinterpret_cast<float4*>(wA + o * KCH + 4 * col) = v;
    }
}

// one matvec pass: 8 channels (8*og+c) x 8 pixels (4*pg.. , 4*pg+32..)
__device__ __forceinline__ void mv_pass(const float* __restrict__ Wg,
                                        const float* __restrict__ data,
                                        float* wA, u64 (&acc)[32],
                                        int og, int pg, int t) {
    #pragma unroll 1
    for (int ch = 0; ch < NCHUNK; ++ch) {
        const int k0 = ch * KCH;
        stage_weights(Wg, wA, k0, t);
        __syncthreads();
        #pragma unroll 1
        for (int m = 0; m < 4; ++m) {
            float4 wq[8];
            #pragma unroll
            for (int c = 0; c < 8; ++c) {
                int row = 8 * og + c;
                int col = (m + row + og) & 3;
                wq[c] = *reinterpret_cast<const float4*>(wA + row * KCH + 4 * col);
            }
            const float* drb = data + (k0 + 4 * m) * PIX + 4 * pg;
            #pragma unroll
            for (int kk = 0; kk < 4; ++kk) {
                const float* dr = drb + kk * PIX;
                ulonglong2 d0 = *reinterpret_cast<const ulonglong2*>(dr);
                ulonglong2 d1 = *reinterpret_cast<const ulonglong2*>(dr + 32);
                #pragma unroll
                for (int c = 0; c < 8; ++c) {
                    float w = (kk == 0) ? wq[c].x : (kk == 1) ? wq[c].y
                            : (kk == 2) ? wq[c].z : wq[c].w;
                    u64 w2 = pack2(w, w);
                    fma2(acc[c*4+0], d0.x, w2); fma2(acc[c*4+1], d0.y, w2);
                    fma2(acc[c*4+2], d1.x, w2); fma2(acc[c*4+3], d1.y, w2);
                }
            }
        }
        __syncthreads();
    }
}

__device__ __forceinline__ void init_acc(u64 (&acc)[32], const float* __restrict__ bias, int og) {
    float4 b0 = *reinterpret_cast<const float4*>(bias + 8 * og);
    float4 b1 = *reinterpret_cast<const float4*>(bias + 8 * og + 4);
    float bb[8] = {b0.x, b0.y, b0.z, b0.w, b1.x, b1.y, b1.z, b1.w};
    #pragma unroll
    for (int c = 0; c < 8; ++c) {
        u64 v = pack2(bb[c], bb[c]);
        #pragma unroll
        for (int i = 0; i < 4; ++i) acc[c * 4 + i] = v;
    }
}

__device__ __forceinline__ void store_acc(u64 (&acc)[32], float* dst, int og, int pg) {
    #pragma unroll
    for (int c = 0; c < 8; ++c) {
        ulonglong2 v0; v0.x = acc[c*4+0]; v0.y = acc[c*4+1];
        ulonglong2 v1; v1.x = acc[c*4+2]; v1.y = acc[c*4+3];
        float* p = dst + (8*og + c) * PIX + 4 * pg;
        *reinterpret_cast<ulonglong2*>(p)      = v0;
        *reinterpret_cast<ulonglong2*>(p + 32) = v1;
    }
}

__global__ void __launch_bounds__(NTHR, 2)
CM_29540785062535_kernel(const float* __restrict__ x,
                         const float* __restrict__ xl,
                         const float* __restrict__ fw,
                         const float* __restrict__ fb,
                         const float* __restrict__ hwm,
                         const float* __restrict__ hb,
                         const float* __restrict__ pw,
                         const float* __restrict__ pb,
                         const float* __restrict__ lnw,
                         const float* __restrict__ lnb,
                         float* __restrict__ out,
                         int Nn)
{
    extern __shared__ float sm[];
    float* xs   = sm + OFF_XS;
    float* ctxs = sm + OFF_CT;
    float* wA   = sm + OFF_WA;
    float* gs   = sm + OFF_GS;
    float* mus  = sm + OFF_MU;
    float* rss  = sm + OFF_RS;

    const int t  = threadIdx.x;
    const int og = t >> 3;        // 0..23 : channels 8*og..8*og+7
    const int pg = t & 7;         // 0..7  : pixels 4*pg..4*pg+3 and +32
    const int b  = blockIdx.x;
    const int n  = b >> 8;        // 256 tiles per image
    const int hw0 = (b & 255) << 6;

    // ---- stage x tile [c][pos] ----
    {
        const float* xb = x + ((size_t)n * CCH) * HWSZ + hw0;
        #pragma unroll 4
        for (int u = 0; u < 16; ++u) {
            int f4 = t + u * NTHR;
            int c = f4 >> 4, L = f4 & 15;
            *reinterpret_cast<float4*>(xs + c * PIX + 4 * L) =
                *reinterpret_cast<const float4*>(xb + (size_t)c * HWSZ + 4 * L);
        }
    }
    __syncthreads();

    // ---- gates: one (l, pixel) slot per thread ----
    {
        int l = t >> 6, p = t & 63;
        const float* wrow = fw + (size_t)(CCH + l) * CCH;
        float a0 = 0.f, a1 = 0.f, a2 = 0.f, a3 = 0.f;
        #pragma unroll 4
        for (int k = 0; k < CCH; k += 4) {
            float4 wv = *reinterpret_cast<const float4*>(wrow + k);
            a0 = fmaf(wv.x, xs[(k+0)*PIX + p], a0);
            a1 = fmaf(wv.y, xs[(k+1)*PIX + p], a1);
            a2 = fmaf(wv.z, xs[(k+2)*PIX + p], a2);
            a3 = fmaf(wv.w, xs[(k+3)*PIX + p], a3);
        }
        gs[t] = (a0 + a1) + (a2 + a3) + fb[CCH + l];
    }
    __syncthreads();

    // ---- ctx = sum_l gates[l] * x_list[l] (streamed), [c][pos] ----
    #pragma unroll 1
    for (int jj = 0; jj < 2; ++jj) {
        float4 ca[8];
        #pragma unroll
        for (int l = 0; l < LG; ++l) {
            const float* src = xl + ((size_t)(l * Nn + n) * CCH) * HWSZ + hw0;
            #pragma unroll
            for (int j = 0; j < 8; ++j) {
                int f4 = t + (jj * 8 + j) * NTHR;
                int c = f4 >> 4, L = f4 & 15;
                float4 v  = *reinterpret_cast<const float4*>(src + (size_t)c * HWSZ + 4 * L);
                float4 g4 = *reinterpret_cast<const float4*>(gs + l * PIX + 4 * L);
                if (l == 0) {
                    ca[j].x = g4.x * v.x; ca[j].y = g4.y * v.y;
                    ca[j].z = g4.z * v.z; ca[j].w = g4.w * v.w;
                } else {
                    ca[j].x = fmaf(g4.x, v.x, ca[j].x);
                    ca[j].y = fmaf(g4.y, v.y, ca[j].y);
                    ca[j].z = fmaf(g4.z, v.z, ca[j].z);
                    ca[j].w = fmaf(g4.w, v.w, ca[j].w);
                }
            }
        }
        #pragma unroll
        for (int j = 0; j < 8; ++j) {
            int f4 = t + (jj * 8 + j) * NTHR;
            int c = f4 >> 4, L = f4 & 15;
            *reinterpret_cast<float4*>(ctxs + c * PIX + 4 * L) = ca[j];
        }
    }
    __syncthreads();

    u64 acc[32];

    // ---- pass 1: mod = hw @ ctx -> ctxs ----
    init_acc(acc, hb, og);
    mv_pass(hwm, ctxs, wA, acc, og, pg, t);
    store_acc(acc, ctxs, og, pg);
    __syncthreads();

    // ---- pass 2: q = fw[:C] @ x ; t = q * mod -> ctxs ----
    init_acc(acc, fb, og);
    mv_pass(fw, xs, wA, acc, og, pg, t);
    #pragma unroll
    for (int c = 0; c < 8; ++c) {
        float* p = ctxs + (8*og + c) * PIX + 4 * pg;
        ulonglong2 m0 = *reinterpret_cast<const ulonglong2*>(p);
        ulonglong2 m1 = *reinterpret_cast<const ulonglong2*>(p + 32);
        m0.x = mul2(acc[c*4+0], m0.x);  m0.y = mul2(acc[c*4+1], m0.y);
        m1.x = mul2(acc[c*4+2], m1.x);  m1.y = mul2(acc[c*4+3], m1.y);
        *reinterpret_cast<ulonglong2*>(p)      = m0;
        *reinterpret_cast<ulonglong2*>(p + 32) = m1;
    }
    __syncthreads();

    // ---- pass 3: y = pw @ t -> ctxs ----
    init_acc(acc, pb, og);
    mv_pass(pw, ctxs, wA, acc, og, pg, t);
    store_acc(acc, ctxs, og, pg);
    __syncthreads();

    // ---- LN stats: 3 channel-segments x 64 pixels ----
    {
        float* ps = wA;          // 192 partial sums
        float* qs = wA + 192;    // 192 partial sumsq
        int seg = t >> 6, px = t & 63;
        float s = 0.f, q = 0.f;
        const float* base = ctxs + seg * 64 * PIX + px;
        #pragma unroll 8
        for (int c = 0; c < 64; ++c) {
            float v = base[c * PIX];
            s += v;
            q = fmaf(v, v, q);
        }
        ps[t] = s;  qs[t] = q;
        __syncthreads();
        if (t < PIX) {
            float st = ps[t] + ps[t + 64] + ps[t + 128];
            float qt = qs[t] + qs[t + 64] + qs[t + 128];
            float mu  = st * (1.0f / CCH);
            float var = qt * (1.0f / CCH) - mu * mu;
            mus[t] = mu;
            rss[t] = rsqrtf(var + EPSV);
        }
    }
    __syncthreads();

    // ---- normalize + residual + coalesced store ----
    {
        float* ob = out + ((size_t)n * CCH) * HWSZ + hw0;
        #pragma unroll 4
        for (int u = 0; u < 16; ++u) {
            int f4 = t + u * NTHR;
            int c = f4 >> 4, L = f4 & 15;
            float4 y4 = *reinterpret_cast<const float4*>(ctxs + c * PIX + 4 * L);
            float4 x4 = *reinterpret_cast<const float4*>(xs   + c * PIX + 4 * L);
            float4 m4 = *reinterpret_cast<const float4*>(mus + 4 * L);
            float4 r4 = *reinterpret_cast<const float4*>(rss + 4 * L);
            float lw = lnw[c], lb = lnb[c];
            float4 r;
            r.x = fmaf(lw * (y4.x - m4.x), r4.x, lb) + x4.x;
            r.y = fmaf(lw * (y4.y - m4.y), r4.y, lb) + x4.y;
            r.z = fmaf(lw * (y4.z - m4.z), r4.z, lb) + x4.z;
            r.w = fmaf(lw * (y4.w - m4.w), r4.w, lb) + x4.w;
            *reinterpret_cast<float4*>(ob + (size_t)c * HWSZ + 4 * L) = r;
        }
    }
}

extern "C" void kernel_launch(void* const* d_in, const int* in_sizes, int n_in,
                              void* d_out, int out_size) {
    const float* x   = (const float*)d_in[0];
    const float* xl  = (const float*)d_in[1];
    const float* fw  = (const float*)d_in[2];
    const float* fb  = (const float*)d_in[3];
    const float* hwm = (const float*)d_in[4];
    const float* hb  = (const float*)d_in[5];
    const float* pw  = (const float*)d_in[6];
    const float* pb  = (const float*)d_in[7];
    const float* lnw = (const float*)d_in[8];
    const float* lnb = (const float*)d_in[9];
    float* out = (float*)d_out;

    int Nn = in_sizes[0] / (CCH * HWSZ);
    size_t smem = SMEM_FLOATS * sizeof(float);   // 111872 B

    cudaFuncSetAttribute(CM_29540785062535_kernel,
                         cudaFuncAttributeMaxDynamicSharedMemorySize, (int)smem);

    int blocks = Nn * (HWSZ / PIX);   // 16 * 256 = 4096
    CM_29540785062535_kernel<<<blocks, NTHR, smem>>>(
        x, xl, fw, fb, hwm, hb, pw, pb, lnw, lnb, out, Nn);
}

// round 7
// speedup vs baseline: 2.1783x; 1.7167x over previous
#include <cuda_runtime.h>

typedef unsigned int u32;
typedef unsigned short u16;

#define CCH  192
#define HWSZ 16384
#define NTHR 256
#define EPSV 1e-6f

// ---- smem byte offsets ----
#define OFF_AH 0u          // A hi: 128px x 192ch bf16, 384B/row, XOR16 swizzle
#define OFF_AL 49152u      // A lo
#define OFF_TH 98304u      // T (q then t) hi
#define OFF_TL 147456u     // T lo
#define OFF_WH 196608u     // weight chunk hi (32n x 192k) 12288B
#define OFF_WL 208896u     // weight chunk lo
#define OFF_GS 221184u     // gates 3x128 f32
#define OFF_FB 222720u     // fb 196 f32
#define OFF_HB 223504u
#define OFF_PB 224272u
#define OFF_LW 225040u
#define OFF_LB 225808u
#define SMEM_TOTAL 226576
// py (fp32 y, [ch][128px] stride 512B, swizzled) overlays OFF_AH..98304
// LN partials overlay OFF_WH

// pre-converted weights: 18 chunks (3 gemms x 6) of 32 rows x 384B, pre-swizzled
__device__ __align__(16) u16 g_wh[3 * 192 * 192];
__device__ __align__(16) u16 g_wl[3 * 192 * 192];

__device__ __forceinline__ u32 cvt2(float lo, float hi) {
    u32 r; asm("cvt.rn.bf16x2.f32 %0, %1, %2;" : "=r"(r) : "f"(hi), "f"(lo)); return r;
}
__device__ __forceinline__ void split2(float a, float b, u32& h2, u32& l2) {
    h2 = cvt2(a, b);
    float ah = __uint_as_float(h2 << 16);
    float bh = __uint_as_float(h2 & 0xFFFF0000u);
    l2 = cvt2(a - ah, b - bh);
}
__device__ __forceinline__ u32 smem_u32_of(const void* p) {
    u32 a;
    asm("{ .reg .u64 t; cvta.to.shared.u64 t, %1; cvt.u32.u64 %0, t; }" : "=r"(a) : "l"(p));
    return a;
}
__device__ __forceinline__ void ldsm4(u32& r0, u32& r1, u32& r2, u32& r3, u32 a) {
    asm volatile("ldmatrix.sync.aligned.m8n8.x4.shared.b16 {%0,%1,%2,%3}, [%4];"
                 : "=r"(r0), "=r"(r1), "=r"(r2), "=r"(r3) : "r"(a));
}
__device__ __forceinline__ void mma16816(float* d, u32 a0, u32 a1, u32 a2, u32 a3,
                                         u32 b0, u32 b1) {
    asm volatile(
        "mma.sync.aligned.m16n8k16.row.col.f32.bf16.bf16.f32 "
        "{%0,%1,%2,%3}, {%4,%5,%6,%7}, {%8,%9}, {%0,%1,%2,%3};"
        : "+f"(d[0]), "+f"(d[1]), "+f"(d[2]), "+f"(d[3])
        : "r"(a0), "r"(a1), "r"(a2), "r"(a3), "r"(b0), "r"(b1));
}

// ---- pre-kernel: fp32 weights -> bf16 hi/lo, chunked + swizzled ----
__global__ void CM_wconv_kernel(const float* __restrict__ fw,
                                const float* __restrict__ hwm,
                                const float* __restrict__ pw) {
    int idx = blockIdx.x * 256 + threadIdx.x;
    if (idx >= 3 * 192 * 192) return;
    int g = idx / (192 * 192);
    int rem = idx - g * (192 * 192);
    int r = rem / 192, k = rem - (rem / 192) * 192;
    const float* src = (g == 0) ? fw : (g == 1) ? hwm : pw;
    float w = src[r * 192 + k];
    u32 h2 = cvt2(w, 0.f);
    float hf = __uint_as_float(h2 << 16);
    u32 l2 = cvt2(w - hf, 0.f);
    u32 off = ((u32)(g * 6 + (r >> 5)) * 32u + (u32)(r & 31)) * 384u
            + (((u32)(2 * k)) ^ ((u32)(r & 7) << 4));
    g_wh[off >> 1] = (u16)(h2 & 0xFFFFu);
    g_wl[off >> 1] = (u16)(l2 & 0xFFFFu);
}

// one GEMM chunk: 12 k-steps, 4 n-tiles, 3 split-products each
__device__ __forceinline__ void gemm_chunk(u32 smb, u32 offH, u32 offL,
                                           float (&acc)[16], int w, int lane) {
    const u32 aswz = (u32)(lane & 7) << 4;
    const u32 arow = 16u * (u32)w + (u32)(lane & 7) + (u32)((lane >> 3) & 1) * 8u;
    const u32 abh  = smb + offH + arow * 384u;
    const u32 abl  = smb + offL + arow * 384u;
    const u32 axor = (u32)((lane >> 4) & 1) * 16u;
    const u32 bb   = smb + ((lane < 16) ? OFF_WH : OFF_WL) + (u32)(lane & 7) * 384u;
    const u32 bxor = (u32)((lane >> 3) & 1) * 16u;
    #pragma unroll
    for (int ks = 0; ks < 12; ++ks) {
        u32 ao = (32u * (u32)ks + axor) ^ aswz;
        u32 ah0, ah1, ah2, ah3, al0, al1, al2, al3;
        ldsm4(ah0, ah1, ah2, ah3, abh + ao);
        ldsm4(al0, al1, al2, al3, abl + ao);
        u32 bo = (32u * (u32)ks + bxor) ^ aswz;
        #pragma unroll
        for (int nt = 0; nt < 4; ++nt) {
            u32 b0, b1, b2, b3;
            ldsm4(b0, b1, b2, b3, bb + (u32)nt * 3072u + bo);
            mma16816(&acc[4 * nt], ah0, ah1, ah2, ah3, b0, b1);  // hh
            mma16816(&acc[4 * nt], ah0, ah1, ah2, ah3, b2, b3);  // h*lo(B)
            mma16816(&acc[4 * nt], al0, al1, al2, al3, b0, b1);  // lo(A)*h
        }
    }
}

__global__ void __launch_bounds__(NTHR, 1)
CM_29540785062535_kernel(const float* __restrict__ x,
                         const float* __restrict__ xl,
                         const float* __restrict__ fw,
                         const float* __restrict__ fbg,
                         const float* __restrict__ hbg,
                         const float* __restrict__ pbg,
                         const float* __restrict__ lnwg,
                         const float* __restrict__ lnbg,
                         float* __restrict__ out,
                         int Nn)
{
    extern __shared__ char smem[];
    const u32 smb = smem_u32_of(smem);
    const int t    = threadIdx.x;
    const int lane = t & 31;
    const int w    = t >> 5;

    const int n   = blockIdx.x >> 7;
    const int hw0 = (blockIdx.x & 127) << 7;

    float* sfb = (float*)(smem + OFF_FB);
    float* shb = (float*)(smem + OFF_HB);
    float* spb = (float*)(smem + OFF_PB);
    float* slw = (float*)(smem + OFF_LW);
    float* slb = (float*)(smem + OFF_LB);
    float* gsf = (float*)(smem + OFF_GS);

    // biases -> smem
    for (int i = t; i < 195; i += NTHR) sfb[i] = fbg[i];
    for (int i = t; i < 192; i += NTHR) {
        shb[i] = hbg[i]; spb[i] = pbg[i]; slw[i] = lnwg[i]; slb[i] = lnbg[i];
    }

    const int p4  = t >> 3;   // pixel quad 0..31
    const int c2b = t & 7;    // channel-pair base

    // ---- phase 1: stage x -> AH/AL + fused gate partials ----
    {
        const float* xb = x + ((size_t)n * CCH) * HWSZ + hw0;
        float ga[12];
        #pragma unroll
        for (int m = 0; m < 12; ++m) ga[m] = 0.f;
        #pragma unroll 2
        for (int i = 0; i < 12; ++i) {
            int c = 2 * c2b + 16 * i;
            float4 a = *(const float4*)(xb + (size_t)c * HWSZ + 4 * p4);
            float4 b = *(const float4*)(xb + (size_t)(c + 1) * HWSZ + 4 * p4);
            float av[4] = {a.x, a.y, a.z, a.w};
            float bv[4] = {b.x, b.y, b.z, b.w};
            #pragma unroll
            for (int j = 0; j < 4; ++j) {
                u32 h2, l2;
                split2(av[j], bv[j], h2, l2);
                u32 px = (u32)(4 * p4 + j);
                u32 off = px * 384u + (((u32)(2 * c)) ^ ((px & 7u) << 4));
                *(u32*)(smem + OFF_AH + off) = h2;
                *(u32*)(smem + OFF_AL + off) = l2;
            }
            #pragma unroll
            for (int l = 0; l < 3; ++l) {
                float w0 = __ldg(fw + (size_t)(192 + l) * 192 + c);
                float w1 = __ldg(fw + (size_t)(192 + l) * 192 + c + 1);
                #pragma unroll
                for (int j = 0; j < 4; ++j)
                    ga[l * 4 + j] = fmaf(w0, av[j], fmaf(w1, bv[j], ga[l * 4 + j]));
            }
        }
        #pragma unroll
        for (int m = 0; m < 12; ++m) {
            float v = ga[m];
            v += __shfl_xor_sync(0xffffffffu, v, 1);
            v += __shfl_xor_sync(0xffffffffu, v, 2);
            v += __shfl_xor_sync(0xffffffffu, v, 4);
            ga[m] = v;
        }
        if (c2b == 0) {
            #pragma unroll
            for (int l = 0; l < 3; ++l)
                #pragma unroll
                for (int j = 0; j < 4; ++j)
                    gsf[l * 128 + 4 * p4 + j] = ga[l * 4 + j] + __ldg(fbg + 192 + l);
        }
    }
    __syncthreads();

    const int tq = lane & 3;       // col pair
    const int g  = lane >> 2;      // row-in-8
    const int r0 = 16 * w + g;
    const int r1 = r0 + 8;
    uint4 ph[3], pl[3];

    // ---- phase 2: q = x @ fw  (chunks 0..5), q+fb -> TH/TL ----
    {
        const uint4* gh = (const uint4*)g_wh;
        const uint4* gl = (const uint4*)g_wl;
        #pragma unroll
        for (int j = 0; j < 3; ++j) { ph[j] = gh[t + 256 * j]; pl[j] = gl[t + 256 * j]; }
        #pragma unroll 1
        for (int c = 0; c < 6; ++c) {
            __syncthreads();
            #pragma unroll
            for (int j = 0; j < 3; ++j) {
                ((uint4*)(smem + OFF_WH))[t + 256 * j] = ph[j];
                ((uint4*)(smem + OFF_WL))[t + 256 * j] = pl[j];
            }
            __syncthreads();
            if (c < 5) {
                #pragma unroll
                for (int j = 0; j < 3; ++j) {
                    ph[j] = gh[(c + 1) * 768 + t + 256 * j];
                    pl[j] = gl[(c + 1) * 768 + t + 256 * j];
                }
            }
            float acc[16];
            #pragma unroll
            for (int m = 0; m < 16; ++m) acc[m] = 0.f;
            gemm_chunk(smb, OFF_AH, OFF_AL, acc, w, lane);
            #pragma unroll
            for (int nt = 0; nt < 4; ++nt) {
                int ch0 = 32 * c + 8 * nt + 2 * tq;
                u32 ob0 = (u32)r0 * 384u + (((u32)(2 * ch0)) ^ ((u32)g << 4));
                u32 ob1 = (u32)r1 * 384u + (((u32)(2 * ch0)) ^ ((u32)g << 4));
                u32 h2, l2;
                split2(acc[4 * nt + 0] + sfb[ch0], acc[4 * nt + 1] + sfb[ch0 + 1], h2, l2);
                *(u32*)(smem + OFF_TH + ob0) = h2;
                *(u32*)(smem + OFF_TL + ob0) = l2;
                split2(acc[4 * nt + 2] + sfb[ch0], acc[4 * nt + 3] + sfb[ch0 + 1], h2, l2);
                *(u32*)(smem + OFF_TH + ob1) = h2;
                *(u32*)(smem + OFF_TL + ob1) = l2;
            }
        }
    }
    __syncthreads();

    // ---- phase 3: ctx = sum_l gates[l]*x_list[l] -> AH/AL ----
    {
        const float* b0 = xl + ((size_t)(0 * Nn + n) * CCH) * HWSZ + hw0;
        const float* b1 = xl + ((size_t)(1 * Nn + n) * CCH) * HWSZ + hw0;
        const float* b2 = xl + ((size_t)(2 * Nn + n) * CCH) * HWSZ + hw0;
        float4 g0 = *(const float4*)(gsf + 0 * 128 + 4 * p4);
        float4 g1 = *(const float4*)(gsf + 1 * 128 + 4 * p4);
        float4 g2 = *(const float4*)(gsf + 2 * 128 + 4 * p4);
        float g0v[4] = {g0.x, g0.y, g0.z, g0.w};
        float g1v[4] = {g1.x, g1.y, g1.z, g1.w};
        float g2v[4] = {g2.x, g2.y, g2.z, g2.w};
        #pragma unroll 2
        for (int i = 0; i < 12; ++i) {
            int c = 2 * c2b + 16 * i;
            size_t oa = (size_t)c * HWSZ + 4 * p4;
            size_t ob = oa + HWSZ;
            float4 a0 = *(const float4*)(b0 + oa), a1 = *(const float4*)(b1 + oa), a2 = *(const float4*)(b2 + oa);
            float4 c0 = *(const float4*)(b0 + ob), c1 = *(const float4*)(b1 + ob), c2 = *(const float4*)(b2 + ob);
            float a0v[4] = {a0.x, a0.y, a0.z, a0.w};
            float a1v[4] = {a1.x, a1.y, a1.z, a1.w};
            float a2v[4] = {a2.x, a2.y, a2.z, a2.w};
            float c0v[4] = {c0.x, c0.y, c0.z, c0.w};
            float c1v[4] = {c1.x, c1.y, c1.z, c1.w};
            float c2v[4] = {c2.x, c2.y, c2.z, c2.w};
            #pragma unroll
            for (int j = 0; j < 4; ++j) {
                float va = fmaf(g2v[j], a2v[j], fmaf(g1v[j], a1v[j], g0v[j] * a0v[j]));
                float vb = fmaf(g2v[j], c2v[j], fmaf(g1v[j], c1v[j], g0v[j] * c0v[j]));
                u32 h2, l2;
                split2(va, vb, h2, l2);
                u32 px = (u32)(4 * p4 + j);
                u32 off = px * 384u + (((u32)(2 * c)) ^ ((px & 7u) << 4));
                *(u32*)(smem + OFF_AH + off) = h2;
                *(u32*)(smem + OFF_AL + off) = l2;
            }
        }
    }
    __syncthreads();

    // ---- phase 4: mod = ctx @ hw; t = q*(mod+hb) -> TH/TL in place ----
    {
        const uint4* gh = (const uint4*)g_wh;
        const uint4* gl = (const uint4*)g_wl;
        #pragma unroll
        for (int j = 0; j < 3; ++j) { ph[j] = gh[6 * 768 + t + 256 * j]; pl[j] = gl[6 * 768 + t + 256 * j]; }
        #pragma unroll 1
        for (int c = 0; c < 6; ++c) {
            __syncthreads();
            #pragma unroll
            for (int j = 0; j < 3; ++j) {
                ((uint4*)(smem + OFF_WH))[t + 256 * j] = ph[j];
                ((uint4*)(smem + OFF_WL))[t + 256 * j] = pl[j];
            }
            __syncthreads();
            if (c < 5) {
                #pragma unroll
                for (int j = 0; j < 3; ++j) {
                    ph[j] = gh[(7 + c) * 768 + t + 256 * j];
                    pl[j] = gl[(7 + c) * 768 + t + 256 * j];
                }
            }
            float acc[16];
            #pragma unroll
            for (int m = 0; m < 16; ++m) acc[m] = 0.f;
            gemm_chunk(smb, OFF_AH, OFF_AL, acc, w, lane);
            #pragma unroll
            for (int nt = 0; nt < 4; ++nt) {
                int ch0 = 32 * c + 8 * nt + 2 * tq;
                u32 ob0 = (u32)r0 * 384u + (((u32)(2 * ch0)) ^ ((u32)g << 4));
                u32 ob1 = (u32)r1 * 384u + (((u32)(2 * ch0)) ^ ((u32)g << 4));
                u32 qh = *(u32*)(smem + OFF_TH + ob0);
                u32 ql = *(u32*)(smem + OFF_TL + ob0);
                float q0 = __uint_as_float(qh << 16) + __uint_as_float(ql << 16);
                float q1 = __uint_as_float(qh & 0xFFFF0000u) + __uint_as_float(ql & 0xFFFF0000u);
                float t0 = q0 * (acc[4 * nt + 0] + shb[ch0]);
                float t1 = q1 * (acc[4 * nt + 1] + shb[ch0 + 1]);
                u32 h2, l2;
                split2(t0, t1, h2, l2);
                *(u32*)(smem + OFF_TH + ob0) = h2;
                *(u32*)(smem + OFF_TL + ob0) = l2;
                qh = *(u32*)(smem + OFF_TH + ob1);
                ql = *(u32*)(smem + OFF_TL + ob1);
                q0 = __uint_as_float(qh << 16) + __uint_as_float(ql << 16);
                q1 = __uint_as_float(qh & 0xFFFF0000u) + __uint_as_float(ql & 0xFFFF0000u);
                t0 = q0 * (acc[4 * nt + 2] + shb[ch0]);
                t1 = q1 * (acc[4 * nt + 3] + shb[ch0 + 1]);
                split2(t0, t1, h2, l2);
                *(u32*)(smem + OFF_TH + ob1) = h2;
                *(u32*)(smem + OFF_TL + ob1) = l2;
            }
        }
    }
    __syncthreads();

    // ---- phase 5: y = t @ pw; y+pb -> py fp32 [ch][128px] (overlays A) ----
    {
        const uint4* gh = (const uint4*)g_wh;
        const uint4* gl = (const uint4*)g_wl;
        #pragma unroll
        for (int j = 0; j < 3; ++j) { ph[j] = gh[12 * 768 + t + 256 * j]; pl[j] = gl[12 * 768 + t + 256 * j]; }
        #pragma unroll 1
        for (int c = 0; c < 6; ++c) {
            __syncthreads();
            #pragma unroll
            for (int j = 0; j < 3; ++j) {
                ((uint4*)(smem + OFF_WH))[t + 256 * j] = ph[j];
                ((uint4*)(smem + OFF_WL))[t + 256 * j] = pl[j];
            }
            __syncthreads();
            if (c < 5) {
                #pragma unroll
                for (int j = 0; j < 3; ++j) {
                    ph[j] = gh[(13 + c) * 768 + t + 256 * j];
                    pl[j] = gl[(13 + c) * 768 + t + 256 * j];
                }
            }
            float acc[16];
            #pragma unroll
            for (int m = 0; m < 16; ++m) acc[m] = 0.f;
            gemm_chunk(smb, OFF_TH, OFF_TL, acc, w, lane);
            #pragma unroll
            for (int nt = 0; nt < 4; ++nt) {
                int ch0 = 32 * c + 8 * nt + 2 * tq;
                u32 s0 = (u32)ch0 * 512u + (((u32)(4 * r0)) ^ (((u32)ch0 & 7u) << 4));
                u32 s1 = (u32)(ch0 + 1) * 512u + (((u32)(4 * r0)) ^ (((u32)(ch0 + 1) & 7u) << 4));
                u32 s2 = (u32)ch0 * 512u + (((u32)(4 * r1)) ^ (((u32)ch0 & 7u) << 4));
                u32 s3 = (u32)(ch0 + 1) * 512u + (((u32)(4 * r1)) ^ (((u32)(ch0 + 1) & 7u) << 4));
                *(float*)(smem + s0) = acc[4 * nt + 0] + spb[ch0];
                *(float*)(smem + s1) = acc[4 * nt + 1] + spb[ch0 + 1];
                *(float*)(smem + s2) = acc[4 * nt + 2] + spb[ch0];
                *(float*)(smem + s3) = acc[4 * nt + 3] + spb[ch0 + 1];
            }
        }
    }
    __syncthreads();

    // ---- phase 6: LN stats over py ----
    float* ps  = (float*)(smem + OFF_WH);
    float* qs  = ps + 256;
    float* mus = ps + 512;
    float* rss = ps + 640;
    {
        int px = t & 127, half = t >> 7;
        float s = 0.f, s2 = 0.f;
        #pragma unroll 4
        for (int ch = 96 * half; ch < 96 * half + 96; ++ch) {
            float v = *(float*)(smem + (u32)ch * 512u + (((u32)(4 * px)) ^ (((u32)ch & 7u) << 4)));
            s += v;
            s2 = fmaf(v, v, s2);
        }
        ps[t] = s; qs[t] = s2;
    }
    __syncthreads();
    if (t < 128) {
        float st = ps[t] + ps[t + 128];
        float qt = qs[t] + qs[t + 128];
        float mu  = st * (1.0f / CCH);
        float var = qt * (1.0f / CCH) - mu * mu;
        mus[t] = mu;
        rss[t] = rsqrtf(var + EPSV);
    }
    __syncthreads();

    // ---- phase 7: normalize + residual + coalesced store ----
    {
        const float* xb = x + ((size_t)n * CCH) * HWSZ + hw0;
        float* ob = out + ((size_t)n * CCH) * HWSZ + hw0;
        #pragma unroll 4
        for (int u = 0; u < 24; ++u) {
            int f4 = t + 256 * u;
            int c = f4 >> 5, L = f4 & 31;
            float4 y = *(const float4*)(smem + (u32)c * 512u + (((u32)(16 * L)) ^ (((u32)c & 7u) << 4)));
            float4 xv = *(const float4*)(xb + (size_t)c * HWSZ + 4 * L);
            float4 m = *(const float4*)(mus + 4 * L);
            float4 r = *(const float4*)(rss + 4 * L);
            float lw = slw[c], lb = slb[c];
            float4 o;
            o.x = fmaf(lw * (y.x - m.x), r.x, lb) + xv.x;
            o.y = fmaf(lw * (y.y - m.y), r.y, lb) + xv.y;
            o.z = fmaf(lw * (y.z - m.z), r.z, lb) + xv.z;
            o.w = fmaf(lw * (y.w - m.w), r.w, lb) + xv.w;
            *(float4*)(ob + (size_t)c * HWSZ + 4 * L) = o;
        }
    }
}

extern "C" void kernel_launch(void* const* d_in, const int* in_sizes, int n_in,
                              void* d_out, int out_size) {
    const float* x   = (const float*)d_in[0];
    const float* xl  = (const float*)d_in[1];
    const float* fw  = (const float*)d_in[2];
    const float* fb  = (const float*)d_in[3];
    const float* hwm = (const float*)d_in[4];
    const float* hb  = (const float*)d_in[5];
    const float* pw  = (const float*)d_in[6];
    const float* pb  = (const float*)d_in[7];
    const float* lnw = (const float*)d_in[8];
    const float* lnb = (const float*)d_in[9];
    float* out = (float*)d_out;

    int Nn = in_sizes[0] / (CCH * HWSZ);

    CM_wconv_kernel<<<(3 * 192 * 192 + 255) / 256, 256>>>(fw, hwm, pw);

    cudaFuncSetAttribute(CM_29540785062535_kernel,
                         cudaFuncAttributeMaxDynamicSharedMemorySize, SMEM_TOTAL);

    int blocks = Nn * (HWSZ / 128);   // 2048
    CM_29540785062535_kernel<<<blocks, NTHR, SMEM_TOTAL>>>(
        x, xl, fw, fb, hb, pb, lnw, lnb, out, Nn);
}

// round 8
// speedup vs baseline: 2.1855x; 1.0033x over previous
#include <cuda_runtime.h>

typedef unsigned int u32;
typedef unsigned short u16;

#define CCH  192
#define HWSZ 16384
#define NTHR 256
#define EPSV 1e-6f

// ---- smem byte offsets ----
#define OFF_AH 0u          // A hi: 128px x 192ch bf16, 384B/row, XOR16 swizzle
#define OFF_AL 49152u      // A lo
#define OFF_TH 98304u      // T (q then t) hi
#define OFF_TL 147456u     // T lo
#define OFF_WH 196608u     // weight chunk hi (32n x 192k) 12288B
#define OFF_WL 208896u     // weight chunk lo
#define OFF_GS 221184u     // gates 3x128 f32
#define OFF_FB 222720u     // fb 196 f32
#define OFF_HB 223504u
#define OFF_PB 224272u
#define OFF_LW 225040u
#define OFF_LB 225808u
#define SMEM_TOTAL 226576
// py (fp32 y, [ch][128px] stride 512B, swizzled) overlays OFF_AH..98304
// LN partials overlay OFF_WH

// pre-converted weights: 18 chunks (3 gemms x 6) of 32 rows x 384B, pre-swizzled
__device__ __align__(16) u16 g_wh[3 * 192 * 192];
__device__ __align__(16) u16 g_wl[3 * 192 * 192];

__device__ __forceinline__ u32 cvt2(float lo, float hi) {
    u32 r; asm("cvt.rn.bf16x2.f32 %0, %1, %2;" : "=r"(r) : "f"(hi), "f"(lo)); return r;
}
__device__ __forceinline__ void split2(float a, float b, u32& h2, u32& l2) {
    h2 = cvt2(a, b);
    float ah = __uint_as_float(h2 << 16);
    float bh = __uint_as_float(h2 & 0xFFFF0000u);
    l2 = cvt2(a - ah, b - bh);
}
__device__ __forceinline__ u32 smem_u32_of(const void* p) {
    u32 a;
    asm("{ .reg .u64 t; cvta.to.shared.u64 t, %1; cvt.u32.u64 %0, t; }" : "=r"(a) : "l"(p));
    return a;
}
__device__ __forceinline__ void ldsm4(u32& r0, u32& r1, u32& r2, u32& r3, u32 a) {
    asm volatile("ldmatrix.sync.aligned.m8n8.x4.shared.b16 {%0,%1,%2,%3}, [%4];"
                 : "=r"(r0), "=r"(r1), "=r"(r2), "=r"(r3) : "r"(a));
}
__device__ __forceinline__ void mma16816(float* d, u32 a0, u32 a1, u32 a2, u32 a3,
                                         u32 b0, u32 b1) {
    asm volatile(
        "mma.sync.aligned.m16n8k16.row.col.f32.bf16.bf16.f32 "
        "{%0,%1,%2,%3}, {%4,%5,%6,%7}, {%8,%9}, {%0,%1,%2,%3};"
        : "+f"(d[0]), "+f"(d[1]), "+f"(d[2]), "+f"(d[3])
        : "r"(a0), "r"(a1), "r"(a2), "r"(a3), "r"(b0), "r"(b1));
}

// ---- pre-kernel: fp32 weights -> bf16 hi/lo, chunked + swizzled ----
__global__ void CM_wconv_kernel(const float* __restrict__ fw,
                                const float* __restrict__ hwm,
                                const float* __restrict__ pw) {
    int idx = blockIdx.x * 256 + threadIdx.x;
    if (idx >= 3 * 192 * 192) return;
    int g = idx / (192 * 192);
    int rem = idx - g * (192 * 192);
    int r = rem / 192, k = rem - (rem / 192) * 192;
    const float* src = (g == 0) ? fw : (g == 1) ? hwm : pw;
    float w = src[r * 192 + k];
    u32 h2 = cvt2(w, 0.f);
    float hf = __uint_as_float(h2 << 16);
    u32 l2 = cvt2(w - hf, 0.f);
    u32 off = ((u32)(g * 6 + (r >> 5)) * 32u + (u32)(r & 31)) * 384u
            + (((u32)(2 * k)) ^ ((u32)(r & 7) << 4));
    g_wh[off >> 1] = (u16)(h2 & 0xFFFFu);
    g_wl[off >> 1] = (u16)(l2 & 0xFFFFu);
}

// one GEMM chunk: 12 k-steps, 4 n-tiles, 3 split-products each.
// A frags double-buffered across k-steps; B frags hoisted ahead of MMAs.
__device__ __forceinline__ void gemm_chunk(u32 smb, u32 offH, u32 offL,
                                           float (&acc)[16], int w, int lane) {
    const u32 aswz = (u32)(lane & 7) << 4;
    const u32 arow = 16u * (u32)w + (u32)(lane & 7) + (u32)((lane >> 3) & 1) * 8u;
    const u32 abh  = smb + offH + arow * 384u;
    const u32 abl  = smb + offL + arow * 384u;
    const u32 axor = (u32)((lane >> 4) & 1) * 16u;
    const u32 bb   = smb + ((lane < 16) ? OFF_WH : OFF_WL) + (u32)(lane & 7) * 384u;
    const u32 bxor = (u32)((lane >> 3) & 1) * 16u;

    u32 fa[2][8];
    // preload A frags for ks=0
    {
        u32 ao = axor ^ aswz;
        ldsm4(fa[0][0], fa[0][1], fa[0][2], fa[0][3], abh + ao);
        ldsm4(fa[0][4], fa[0][5], fa[0][6], fa[0][7], abl + ao);
    }
    #pragma unroll
    for (int ks = 0; ks < 12; ++ks) {
        const int cur = ks & 1, nxt = cur ^ 1;
        // B frags for current k-step (all 4 n-tiles up front)
        u32 fb[16];
        {
            u32 bo = (32u * (u32)ks + bxor) ^ aswz;
            ldsm4(fb[0],  fb[1],  fb[2],  fb[3],  bb + 0u    + bo);
            ldsm4(fb[4],  fb[5],  fb[6],  fb[7],  bb + 3072u + bo);
            ldsm4(fb[8],  fb[9],  fb[10], fb[11], bb + 6144u + bo);
            ldsm4(fb[12], fb[13], fb[14], fb[15], bb + 9216u + bo);
        }
        // prefetch A frags for next k-step
        if (ks < 11) {
            u32 ao = (32u * (u32)(ks + 1) + axor) ^ aswz;
            ldsm4(fa[nxt][0], fa[nxt][1], fa[nxt][2], fa[nxt][3], abh + ao);
            ldsm4(fa[nxt][4], fa[nxt][5], fa[nxt][6], fa[nxt][7], abl + ao);
        }
        #pragma unroll
        for (int nt = 0; nt < 4; ++nt) {
            mma16816(&acc[4 * nt], fa[cur][0], fa[cur][1], fa[cur][2], fa[cur][3],
                     fb[4 * nt], fb[4 * nt + 1]);                     // hh
            mma16816(&acc[4 * nt], fa[cur][0], fa[cur][1], fa[cur][2], fa[cur][3],
                     fb[4 * nt + 2], fb[4 * nt + 3]);                 // h * lo(B)
            mma16816(&acc[4 * nt], fa[cur][4], fa[cur][5], fa[cur][6], fa[cur][7],
                     fb[4 * nt], fb[4 * nt + 1]);                     // lo(A) * h
        }
    }
}

__global__ void __launch_bounds__(NTHR, 1)
CM_29540785062535_kernel(const float* __restrict__ x,
                         const float* __restrict__ xl,
                         const float* __restrict__ fw,
                         const float* __restrict__ fbg,
                         const float* __restrict__ hbg,
                         const float* __restrict__ pbg,
                         const float* __restrict__ lnwg,
                         const float* __restrict__ lnbg,
                         float* __restrict__ out,
                         int Nn)
{
    extern __shared__ char smem[];
    const u32 smb = smem_u32_of(smem);
    const int t    = threadIdx.x;
    const int lane = t & 31;
    const int w    = t >> 5;

    const int n   = blockIdx.x >> 7;
    const int hw0 = (blockIdx.x & 127) << 7;

    float* sfb = (float*)(smem + OFF_FB);
    float* shb = (float*)(smem + OFF_HB);
    float* spb = (float*)(smem + OFF_PB);
    float* slw = (float*)(smem + OFF_LW);
    float* slb = (float*)(smem + OFF_LB);
    float* gsf = (float*)(smem + OFF_GS);

    // biases -> smem
    for (int i = t; i < 195; i += NTHR) sfb[i] = fbg[i];
    for (int i = t; i < 192; i += NTHR) {
        shb[i] = hbg[i]; spb[i] = pbg[i]; slw[i] = lnwg[i]; slb[i] = lnbg[i];
    }

    const int p4  = t >> 3;   // pixel quad 0..31
    const int c2b = t & 7;    // channel-pair base

    // ---- phase 1: stage x -> AH/AL + fused gate partials ----
    {
        const float* xb = x + ((size_t)n * CCH) * HWSZ + hw0;
        float ga[12];
        #pragma unroll
        for (int m = 0; m < 12; ++m) ga[m] = 0.f;
        #pragma unroll 2
        for (int i = 0; i < 12; ++i) {
            int c = 2 * c2b + 16 * i;
            float4 a = *(const float4*)(xb + (size_t)c * HWSZ + 4 * p4);
            float4 b = *(const float4*)(xb + (size_t)(c + 1) * HWSZ + 4 * p4);
            float av[4] = {a.x, a.y, a.z, a.w};
            float bv[4] = {b.x, b.y, b.z, b.w};
            #pragma unroll
            for (int j = 0; j < 4; ++j) {
                u32 h2, l2;
                split2(av[j], bv[j], h2, l2);
                u32 px = (u32)(4 * p4 + j);
                u32 off = px * 384u + (((u32)(2 * c)) ^ ((px & 7u) << 4));
                *(u32*)(smem + OFF_AH + off) = h2;
                *(u32*)(smem + OFF_AL + off) = l2;
            }
            #pragma unroll
            for (int l = 0; l < 3; ++l) {
                float w0 = __ldg(fw + (size_t)(192 + l) * 192 + c);
                float w1 = __ldg(fw + (size_t)(192 + l) * 192 + c + 1);
                #pragma unroll
                for (int j = 0; j < 4; ++j)
                    ga[l * 4 + j] = fmaf(w0, av[j], fmaf(w1, bv[j], ga[l * 4 + j]));
            }
        }
        #pragma unroll
        for (int m = 0; m < 12; ++m) {
            float v = ga[m];
            v += __shfl_xor_sync(0xffffffffu, v, 1);
            v += __shfl_xor_sync(0xffffffffu, v, 2);
            v += __shfl_xor_sync(0xffffffffu, v, 4);
            ga[m] = v;
        }
        if (c2b == 0) {
            #pragma unroll
            for (int l = 0; l < 3; ++l)
                #pragma unroll
                for (int j = 0; j < 4; ++j)
                    gsf[l * 128 + 4 * p4 + j] = ga[l * 4 + j] + __ldg(fbg + 192 + l);
        }
    }
    __syncthreads();

    const int tq = lane & 3;       // col pair
    const int g  = lane >> 2;      // row-in-8
    const int r0 = 16 * w + g;
    const int r1 = r0 + 8;
    uint4 ph[3], pl[3];

    // ---- phase 2: q = x @ fw  (chunks 0..5), q+fb -> TH/TL ----
    {
        const uint4* gh = (const uint4*)g_wh;
        const uint4* gl = (const uint4*)g_wl;
        #pragma unroll
        for (int j = 0; j < 3; ++j) { ph[j] = gh[t + 256 * j]; pl[j] = gl[t + 256 * j]; }
        #pragma unroll 1
        for (int c = 0; c < 6; ++c) {
            __syncthreads();
            #pragma unroll
            for (int j = 0; j < 3; ++j) {
                ((uint4*)(smem + OFF_WH))[t + 256 * j] = ph[j];
                ((uint4*)(smem + OFF_WL))[t + 256 * j] = pl[j];
            }
            __syncthreads();
            if (c < 5) {
                #pragma unroll
                for (int j = 0; j < 3; ++j) {
                    ph[j] = gh[(c + 1) * 768 + t + 256 * j];
                    pl[j] = gl[(c + 1) * 768 + t + 256 * j];
                }
            }
            float acc[16];
            #pragma unroll
            for (int m = 0; m < 16; ++m) acc[m] = 0.f;
            gemm_chunk(smb, OFF_AH, OFF_AL, acc, w, lane);
            #pragma unroll
            for (int nt = 0; nt < 4; ++nt) {
                int ch0 = 32 * c + 8 * nt + 2 * tq;
                u32 ob0 = (u32)r0 * 384u + (((u32)(2 * ch0)) ^ ((u32)g << 4));
                u32 ob1 = (u32)r1 * 384u + (((u32)(2 * ch0)) ^ ((u32)g << 4));
                u32 h2, l2;
                split2(acc[4 * nt + 0] + sfb[ch0], acc[4 * nt + 1] + sfb[ch0 + 1], h2, l2);
                *(u32*)(smem + OFF_TH + ob0) = h2;
                *(u32*)(smem + OFF_TL + ob0) = l2;
                split2(acc[4 * nt + 2] + sfb[ch0], acc[4 * nt + 3] + sfb[ch0 + 1], h2, l2);
                *(u32*)(smem + OFF_TH + ob1) = h2;
                *(u32*)(smem + OFF_TL + ob1) = l2;
            }
        }
    }
    __syncthreads();

    // ---- phase 3: ctx = sum_l gates[l]*x_list[l] -> AH/AL ----
    {
        const float* b0 = xl + ((size_t)(0 * Nn + n) * CCH) * HWSZ + hw0;
        const float* b1 = xl + ((size_t)(1 * Nn + n) * CCH) * HWSZ + hw0;
        const float* b2 = xl + ((size_t)(2 * Nn + n) * CCH) * HWSZ + hw0;
        float4 g0 = *(const float4*)(gsf + 0 * 128 + 4 * p4);
        float4 g1 = *(const float4*)(gsf + 1 * 128 + 4 * p4);
        float4 g2 = *(const float4*)(gsf + 2 * 128 + 4 * p4);
        float g0v[4] = {g0.x, g0.y, g0.z, g0.w};
        float g1v[4] = {g1.x, g1.y, g1.z, g1.w};
        float g2v[4] = {g2.x, g2.y, g2.z, g2.w};
        #pragma unroll 2
        for (int i = 0; i < 12; ++i) {
            int c = 2 * c2b + 16 * i;
            size_t oa = (size_t)c * HWSZ + 4 * p4;
            size_t ob = oa + HWSZ;
            float4 a0 = *(const float4*)(b0 + oa), a1 = *(const float4*)(b1 + oa), a2 = *(const float4*)(b2 + oa);
            float4 c0 = *(const float4*)(b0 + ob), c1 = *(const float4*)(b1 + ob), c2 = *(const float4*)(b2 + ob);
            float a0v[4] = {a0.x, a0.y, a0.z, a0.w};
            float a1v[4] = {a1.x, a1.y, a1.z, a1.w};
            float a2v[4] = {a2.x, a2.y, a2.z, a2.w};
            float c0v[4] = {c0.x, c0.y, c0.z, c0.w};
            float c1v[4] = {c1.x, c1.y, c1.z, c1.w};
            float c2v[4] = {c2.x, c2.y, c2.z, c2.w};
            #pragma unroll
            for (int j = 0; j < 4; ++j) {
                float va = fmaf(g2v[j], a2v[j], fmaf(g1v[j], a1v[j], g0v[j] * a0v[j]));
                float vb = fmaf(g2v[j], c2v[j], fmaf(g1v[j], c1v[j], g0v[j] * c0v[j]));
                u32 h2, l2;
                split2(va, vb, h2, l2);
                u32 px = (u32)(4 * p4 + j);
                u32 off = px * 384u + (((u32)(2 * c)) ^ ((px & 7u) << 4));
                *(u32*)(smem + OFF_AH + off) = h2;
                *(u32*)(smem + OFF_AL + off) = l2;
            }
        }
    }
    __syncthreads();

    // ---- phase 4: mod = ctx @ hw; t = q*(mod+hb) -> TH/TL in place ----
    {
        const uint4* gh = (const uint4*)g_wh;
        const uint4* gl = (const uint4*)g_wl;
        #pragma unroll
        for (int j = 0; j < 3; ++j) { ph[j] = gh[6 * 768 + t + 256 * j]; pl[j] = gl[6 * 768 + t + 256 * j]; }
        #pragma unroll 1
        for (int c = 0; c < 6; ++c) {
            __syncthreads();
            #pragma unroll
            for (int j = 0; j < 3; ++j) {
                ((uint4*)(smem + OFF_WH))[t + 256 * j] = ph[j];
                ((uint4*)(smem + OFF_WL))[t + 256 * j] = pl[j];
            }
            __syncthreads();
            if (c < 5) {
                #pragma unroll
                for (int j = 0; j < 3; ++j) {
                    ph[j] = gh[(7 + c) * 768 + t + 256 * j];
                    pl[j] = gl[(7 + c) * 768 + t + 256 * j];
                }
            }
            float acc[16];
            #pragma unroll
            for (int m = 0; m < 16; ++m) acc[m] = 0.f;
            gemm_chunk(smb, OFF_AH, OFF_AL, acc, w, lane);
            #pragma unroll
            for (int nt = 0; nt < 4; ++nt) {
                int ch0 = 32 * c + 8 * nt + 2 * tq;
                u32 ob0 = (u32)r0 * 384u + (((u32)(2 * ch0)) ^ ((u32)g << 4));
                u32 ob1 = (u32)r1 * 384u + (((u32)(2 * ch0)) ^ ((u32)g << 4));
                u32 qh = *(u32*)(smem + OFF_TH + ob0);
                u32 ql = *(u32*)(smem + OFF_TL + ob0);
                float q0 = __uint_as_float(qh << 16) + __uint_as_float(ql << 16);
                float q1 = __uint_as_float(qh & 0xFFFF0000u) + __uint_as_float(ql & 0xFFFF0000u);
                float t0 = q0 * (acc[4 * nt + 0] + shb[ch0]);
                float t1 = q1 * (acc[4 * nt + 1] + shb[ch0 + 1]);
                u32 h2, l2;
                split2(t0, t1, h2, l2);
                *(u32*)(smem + OFF_TH + ob0) = h2;
                *(u32*)(smem + OFF_TL + ob0) = l2;
                qh = *(u32*)(smem + OFF_TH + ob1);
                ql = *(u32*)(smem + OFF_TL + ob1);
                q0 = __uint_as_float(qh << 16) + __uint_as_float(ql << 16);
                q1 = __uint_as_float(qh & 0xFFFF0000u) + __uint_as_float(ql & 0xFFFF0000u);
                t0 = q0 * (acc[4 * nt + 2] + shb[ch0]);
                t1 = q1 * (acc[4 * nt + 3] + shb[ch0 + 1]);
                split2(t0, t1, h2, l2);
                *(u32*)(smem + OFF_TH + ob1) = h2;
                *(u32*)(smem + OFF_TL + ob1) = l2;
            }
        }
    }
    __syncthreads();

    // ---- phase 5: y = t @ pw; y+pb -> py fp32 [ch][128px] (overlays A) ----
    {
        const uint4* gh = (const uint4*)g_wh;
        const uint4* gl = (const uint4*)g_wl;
        #pragma unroll
        for (int j = 0; j < 3; ++j) { ph[j] = gh[12 * 768 + t + 256 * j]; pl[j] = gl[12 * 768 + t + 256 * j]; }
        #pragma unroll 1
        for (int c = 0; c < 6; ++c) {
            __syncthreads();
            #pragma unroll
            for (int j = 0; j < 3; ++j) {
                ((uint4*)(smem + OFF_WH))[t + 256 * j] = ph[j];
                ((uint4*)(smem + OFF_WL))[t + 256 * j] = pl[j];
            }
            __syncthreads();
            if (c < 5) {
                #pragma unroll
                for (int j = 0; j < 3; ++j) {
                    ph[j] = gh[(13 + c) * 768 + t + 256 * j];
                    pl[j] = gl[(13 + c) * 768 + t + 256 * j];
                }
            }
            float acc[16];
            #pragma unroll
            for (int m = 0; m < 16; ++m) acc[m] = 0.f;
            gemm_chunk(smb, OFF_TH, OFF_TL, acc, w, lane);
            #pragma unroll
            for (int nt = 0; nt < 4; ++nt) {
                int ch0 = 32 * c + 8 * nt + 2 * tq;
                u32 s0 = (u32)ch0 * 512u + (((u32)(4 * r0)) ^ (((u32)ch0 & 7u) << 4));
                u32 s1 = (u32)(ch0 + 1) * 512u + (((u32)(4 * r0)) ^ (((u32)(ch0 + 1) & 7u) << 4));
                u32 s2 = (u32)ch0 * 512u + (((u32)(4 * r1)) ^ (((u32)ch0 & 7u) << 4));
                u32 s3 = (u32)(ch0 + 1) * 512u + (((u32)(4 * r1)) ^ (((u32)(ch0 + 1) & 7u) << 4));
                *(float*)(smem + s0) = acc[4 * nt + 0] + spb[ch0];
                *(float*)(smem + s1) = acc[4 * nt + 1] + spb[ch0 + 1];
                *(float*)(smem + s2) = acc[4 * nt + 2] + spb[ch0];
                *(float*)(smem + s3) = acc[4 * nt + 3] + spb[ch0 + 1];
            }
        }
    }
    __syncthreads();

    // ---- phase 6: LN stats over py ----
    float* ps  = (float*)(smem + OFF_WH);
    float* qs  = ps + 256;
    float* mus = ps + 512;
    float* rss = ps + 640;
    {
        int px = t & 127, half = t >> 7;
        float s = 0.f, s2 = 0.f;
        #pragma unroll 4
        for (int ch = 96 * half; ch < 96 * half + 96; ++ch) {
            float v = *(float*)(smem + (u32)ch * 512u + (((u32)(4 * px)) ^ (((u32)ch & 7u) << 4)));
            s += v;
            s2 = fmaf(v, v, s2);
        }
        ps[t] = s; qs[t] = s2;
    }
    __syncthreads();
    if (t < 128) {
        float st = ps[t] + ps[t + 128];
        float qt = qs[t] + qs[t + 128];
        float mu  = st * (1.0f / CCH);
        float var = qt * (1.0f / CCH) - mu * mu;
        mus[t] = mu;
        rss[t] = rsqrtf(var + EPSV);
    }
    __syncthreads();

    // ---- phase 7: normalize + residual + coalesced store ----
    {
        const float* xb = x + ((size_t)n * CCH) * HWSZ + hw0;
        float* ob = out + ((size_t)n * CCH) * HWSZ + hw0;
        #pragma unroll 4
        for (int u = 0; u < 24; ++u) {
            int f4 = t + 256 * u;
            int c = f4 >> 5, L = f4 & 31;
            float4 y = *(const float4*)(smem + (u32)c * 512u + (((u32)(16 * L)) ^ (((u32)c & 7u) << 4)));
            float4 xv = *(const float4*)(xb + (size_t)c * HWSZ + 4 * L);
            float4 m = *(const float4*)(mus + 4 * L);
            float4 r = *(const float4*)(rss + 4 * L);
            float lw = slw[c], lb = slb[c];
            float4 o;
            o.x = fmaf(lw * (y.x - m.x), r.x, lb) + xv.x;
            o.y = fmaf(lw * (y.y - m.y), r.y, lb) + xv.y;
            o.z = fmaf(lw * (y.z - m.z), r.z, lb) + xv.z;
            o.w = fmaf(lw * (y.w - m.w), r.w, lb) + xv.w;
            *(float4*)(ob + (size_t)c * HWSZ + 4 * L) = o;
        }
    }
}

extern "C" void kernel_launch(void* const* d_in, const int* in_sizes, int n_in,
                              void* d_out, int out_size) {
    const float* x   = (const float*)d_in[0];
    const float* xl  = (const float*)d_in[1];
    const float* fw  = (const float*)d_in[2];
    const float* fb  = (const float*)d_in[3];
    const float* hwm = (const float*)d_in[4];
    const float* hb  = (const float*)d_in[5];
    const float* pw  = (const float*)d_in[6];
    const float* pb  = (const float*)d_in[7];
    const float* lnw = (const float*)d_in[8];
    const float* lnb = (const float*)d_in[9];
    float* out = (float*)d_out;

    int Nn = in_sizes[0] / (CCH * HWSZ);

    CM_wconv_kernel<<<(3 * 192 * 192 + 255) / 256, 256>>>(fw, hwm, pw);

    cudaFuncSetAttribute(CM_29540785062535_kernel,
                         cudaFuncAttributeMaxDynamicSharedMemorySize, SMEM_TOTAL);

    int blocks = Nn * (HWSZ / 128);   // 2048
    CM_29540785062535_kernel<<<blocks, NTHR, SMEM_TOTAL>>>(
        x, xl, fw, fb, hb, pb, lnw, lnb, out, Nn);
}

// round 9
// speedup vs baseline: 2.3223x; 1.0626x over previous
#include <cuda_runtime.h>

typedef unsigned int u32;
typedef unsigned short u16;

#define CCH  192
#define HWSZ 16384
#define NTHR 256
#define EPSV 1e-6f

// ---- smem byte offsets ----
#define OFF_AH 0u          // A hi: 128px x 192ch bf16, 384B/row, XOR16 swizzle
#define OFF_AL 49152u      // A lo
#define OFF_TH 98304u      // T (q then t) hi
#define OFF_TL 147456u     // T lo
#define OFF_W  196608u     // weight half-chunk: 64n x (96k hi | 96k lo) = 384B/row, 24576B
#define OFF_GS 221184u     // gates 3x128 f32
#define OFF_FB 222720u     // fb 196 f32
#define OFF_HB 223504u
#define OFF_PB 224272u
#define OFF_LW 225040u
#define OFF_LB 225808u
#define SMEM_TOTAL 226576
// py (fp32 y, [ch][128px] stride 512B, swizzled) overlays OFF_AH..98304
// LN partials overlay OFF_W

// pre-converted weights: 18 regions = 3 gemms x 3 chunks(64n) x 2 k-halves(96k),
// each 64 rows x 384B (hi|lo), pre-swizzled. 442368 B total.
__device__ __align__(16) u16 g_wc[221184];

__device__ __forceinline__ u32 cvt2(float lo, float hi) {
    u32 r; asm("cvt.rn.bf16x2.f32 %0, %1, %2;" : "=r"(r) : "f"(hi), "f"(lo)); return r;
}
__device__ __forceinline__ void split2(float a, float b, u32& h2, u32& l2) {
    h2 = cvt2(a, b);
    float ah = __uint_as_float(h2 << 16);
    float bh = __uint_as_float(h2 & 0xFFFF0000u);
    l2 = cvt2(a - ah, b - bh);
}
__device__ __forceinline__ u32 smem_u32_of(const void* p) {
    u32 a;
    asm("{ .reg .u64 t; cvta.to.shared.u64 t, %1; cvt.u32.u64 %0, t; }" : "=r"(a) : "l"(p));
    return a;
}
__device__ __forceinline__ void ldsm4(u32& r0, u32& r1, u32& r2, u32& r3, u32 a) {
    asm volatile("ldmatrix.sync.aligned.m8n8.x4.shared.b16 {%0,%1,%2,%3}, [%4];"
                 : "=r"(r0), "=r"(r1), "=r"(r2), "=r"(r3) : "r"(a));
}
__device__ __forceinline__ void mma16816(float* d, u32 a0, u32 a1, u32 a2, u32 a3,
                                         u32 b0, u32 b1) {
    asm volatile(
        "mma.sync.aligned.m16n8k16.row.col.f32.bf16.bf16.f32 "
        "{%0,%1,%2,%3}, {%4,%5,%6,%7}, {%8,%9}, {%0,%1,%2,%3};"
        : "+f"(d[0]), "+f"(d[1]), "+f"(d[2]), "+f"(d[3])
        : "r"(a0), "r"(a1), "r"(a2), "r"(a3), "r"(b0), "r"(b1));
}

// ---- pre-kernel: fp32 weights -> bf16 hi/lo, region layout ----
__global__ void CM_wconv_kernel(const float* __restrict__ fw,
                                const float* __restrict__ hwm,
                                const float* __restrict__ pw) {
    int idx = blockIdx.x * 256 + threadIdx.x;
    if (idx >= 3 * 192 * 192) return;
    int g = idx / (192 * 192);
    int rem = idx - g * (192 * 192);
    int r = rem / 192, k = rem - (rem / 192) * 192;
    const float* src = (g == 0) ? fw : (g == 1) ? hwm : pw;
    float w = src[r * 192 + k];
    u32 h2 = cvt2(w, 0.f);
    float hf = __uint_as_float(h2 << 16);
    u32 l2 = cvt2(w - hf, 0.f);
    int c = r >> 6, rr = r & 63;
    int h = (k >= 96) ? 1 : 0, kk = k - 96 * h;
    u32 base = (u32)((g * 3 + c) * 2 + h) * 24576u + (u32)rr * 384u;
    u32 sw = ((u32)rr & 7u) << 4;
    g_wc[(base + (((u32)(2 * kk)) ^ sw)) >> 1]       = (u16)(h2 & 0xFFFFu);
    g_wc[(base + (((u32)(192 + 2 * kk)) ^ sw)) >> 1] = (u16)(l2 & 0xFFFFu);
}

// stage one 24576B weight region from ph regs -> smem, prefetch region nidx
__device__ __forceinline__ void stage_w(char* smem, uint4 (&ph)[6], int nidx, int t) {
    __syncthreads();
    #pragma unroll
    for (int j = 0; j < 6; ++j) ((uint4*)(smem + OFF_W))[t + 256 * j] = ph[j];
    __syncthreads();
    if (nidx < 18) {
        const uint4* gw = (const uint4*)g_wc;
        #pragma unroll
        for (int j = 0; j < 6; ++j) ph[j] = gw[(size_t)nidx * 1536 + t + 256 * j];
    }
}

// one K-half: 6 k-steps, Mt=2 x Nt=4 warp tile, 3 split-products
__device__ __forceinline__ void gemm_half(u32 smb, u32 offH, u32 offL, u32 kbase,
                                          float (&acc)[32], int wm, int wn, int lane) {
    const u32 aswz = (u32)(lane & 7) << 4;
    const u32 arow = 32u * (u32)wm + (u32)(lane & 7) + ((u32)(lane >> 3) & 1u) * 8u;
    const u32 abh  = smb + offH + arow * 384u;
    const u32 abl  = smb + offL + arow * 384u;
    const u32 axor = ((u32)(lane >> 4) & 1u) * 16u;
    const u32 brow = 32u * (u32)wn + (u32)(lane & 7);
    const u32 bb   = smb + OFF_W + brow * 384u;
    const u32 bcol0 = ((u32)(lane >> 4) & 1u) * 192u + ((u32)(lane >> 3) & 1u) * 16u;
    #pragma unroll
    for (int ks = 0; ks < 6; ++ks) {
        u32 acol = (kbase + 32u * (u32)ks + axor) ^ aswz;
        u32 fa[16];
        ldsm4(fa[0],  fa[1],  fa[2],  fa[3],  abh + acol);
        ldsm4(fa[4],  fa[5],  fa[6],  fa[7],  abl + acol);
        ldsm4(fa[8],  fa[9],  fa[10], fa[11], abh + 6144u + acol);
        ldsm4(fa[12], fa[13], fa[14], fa[15], abl + 6144u + acol);
        u32 bcol = (bcol0 + 32u * (u32)ks) ^ aswz;
        u32 fb[16];
        ldsm4(fb[0],  fb[1],  fb[2],  fb[3],  bb + bcol);
        ldsm4(fb[4],  fb[5],  fb[6],  fb[7],  bb + 3072u + bcol);
        ldsm4(fb[8],  fb[9],  fb[10], fb[11], bb + 6144u + bcol);
        ldsm4(fb[12], fb[13], fb[14], fb[15], bb + 9216u + bcol);
        #pragma unroll
        for (int mt = 0; mt < 2; ++mt)
            #pragma unroll
            for (int nt = 0; nt < 4; ++nt) {
                float* a = &acc[mt * 16 + nt * 4];
                mma16816(a, fa[8*mt+0], fa[8*mt+1], fa[8*mt+2], fa[8*mt+3],
                         fb[4*nt+0], fb[4*nt+1]);                          // hh
                mma16816(a, fa[8*mt+0], fa[8*mt+1], fa[8*mt+2], fa[8*mt+3],
                         fb[4*nt+2], fb[4*nt+3]);                          // h*lo(B)
                mma16816(a, fa[8*mt+4], fa[8*mt+5], fa[8*mt+6], fa[8*mt+7],
                         fb[4*nt+0], fb[4*nt+1]);                          // lo(A)*h
            }
    }
}

__global__ void __launch_bounds__(NTHR, 1)
CM_29540785062535_kernel(const float* __restrict__ x,
                         const float* __restrict__ xl,
                         const float* __restrict__ fw,
                         const float* __restrict__ fbg,
                         const float* __restrict__ hbg,
                         const float* __restrict__ pbg,
                         const float* __restrict__ lnwg,
                         const float* __restrict__ lnbg,
                         float* __restrict__ out,
                         int Nn)
{
    extern __shared__ char smem[];
    const u32 smb = smem_u32_of(smem);
    const int t    = threadIdx.x;
    const int lane = t & 31;
    const int w    = t >> 5;
    const int wm   = w & 3;        // M row (32px)
    const int wn   = w >> 2;       // N col (32ch within 64-chunk)

    const int n   = blockIdx.x >> 7;
    const int hw0 = (blockIdx.x & 127) << 7;

    float* sfb = (float*)(smem + OFF_FB);
    float* shb = (float*)(smem + OFF_HB);
    float* spb = (float*)(smem + OFF_PB);
    float* slw = (float*)(smem + OFF_LW);
    float* slb = (float*)(smem + OFF_LB);
    float* gsf = (float*)(smem + OFF_GS);

    for (int i = t; i < 195; i += NTHR) sfb[i] = fbg[i];
    for (int i = t; i < 192; i += NTHR) {
        shb[i] = hbg[i]; spb[i] = pbg[i]; slw[i] = lnwg[i]; slb[i] = lnbg[i];
    }

    const int p4  = t >> 3;   // pixel quad 0..31
    const int c2b = t & 7;    // channel-pair base

    // ---- phase 1: stage x -> AH/AL + fused gate partials ----
    {
        const float* xb = x + ((size_t)n * CCH) * HWSZ + hw0;
        float ga[12];
        #pragma unroll
        for (int m = 0; m < 12; ++m) ga[m] = 0.f;
        #pragma unroll 2
        for (int i = 0; i < 12; ++i) {
            int c = 2 * c2b + 16 * i;
            float4 a = *(const float4*)(xb + (size_t)c * HWSZ + 4 * p4);
            float4 b = *(const float4*)(xb + (size_t)(c + 1) * HWSZ + 4 * p4);
            float av[4] = {a.x, a.y, a.z, a.w};
            float bv[4] = {b.x, b.y, b.z, b.w};
            #pragma unroll
            for (int j = 0; j < 4; ++j) {
                u32 h2, l2;
                split2(av[j], bv[j], h2, l2);
                u32 px = (u32)(4 * p4 + j);
                u32 off = px * 384u + (((u32)(2 * c)) ^ ((px & 7u) << 4));
                *(u32*)(smem + OFF_AH + off) = h2;
                *(u32*)(smem + OFF_AL + off) = l2;
            }
            #pragma unroll
            for (int l = 0; l < 3; ++l) {
                float w0 = __ldg(fw + (size_t)(192 + l) * 192 + c);
                float w1 = __ldg(fw + (size_t)(192 + l) * 192 + c + 1);
                #pragma unroll
                for (int j = 0; j < 4; ++j)
                    ga[l * 4 + j] = fmaf(w0, av[j], fmaf(w1, bv[j], ga[l * 4 + j]));
            }
        }
        #pragma unroll
        for (int m = 0; m < 12; ++m) {
            float v = ga[m];
            v += __shfl_xor_sync(0xffffffffu, v, 1);
            v += __shfl_xor_sync(0xffffffffu, v, 2);
            v += __shfl_xor_sync(0xffffffffu, v, 4);
            ga[m] = v;
        }
        if (c2b == 0) {
            #pragma unroll
            for (int l = 0; l < 3; ++l)
                #pragma unroll
                for (int j = 0; j < 4; ++j)
                    gsf[l * 128 + 4 * p4 + j] = ga[l * 4 + j] + __ldg(fbg + 192 + l);
        }
    }

    const int tq = lane & 3;       // col pair
    const int gg = lane >> 2;      // row-in-8

    uint4 ph[6];
    {
        const uint4* gw = (const uint4*)g_wc;
        #pragma unroll
        for (int j = 0; j < 6; ++j) ph[j] = gw[t + 256 * j];   // region 0
    }

    // ---- GEMM1: q = x @ fw ; q+fb -> TH/TL ----
    #pragma unroll 1
    for (int c = 0; c < 3; ++c) {
        float acc[32];
        #pragma unroll
        for (int m = 0; m < 32; ++m) acc[m] = 0.f;
        stage_w(smem, ph, 2 * c + 1, t);
        gemm_half(smb, OFF_AH, OFF_AL, 0u, acc, wm, wn, lane);
        stage_w(smem, ph, 2 * c + 2, t);
        gemm_half(smb, OFF_AH, OFF_AL, 192u, acc, wm, wn, lane);
        #pragma unroll
        for (int mt = 0; mt < 2; ++mt)
            #pragma unroll
            for (int nt = 0; nt < 4; ++nt) {
                int ch0 = 64 * c + 32 * wn + 8 * nt + 2 * tq;
                int r0 = 32 * wm + 16 * mt + gg;
                const float* a = &acc[mt * 16 + nt * 4];
                u32 sw = (((u32)(2 * ch0)) ^ (((u32)r0 & 7u) << 4));
                u32 o0 = (u32)r0 * 384u + sw;
                u32 o1 = o0 + 8u * 384u;
                u32 h2, l2;
                split2(a[0] + sfb[ch0], a[1] + sfb[ch0 + 1], h2, l2);
                *(u32*)(smem + OFF_TH + o0) = h2;
                *(u32*)(smem + OFF_TL + o0) = l2;
                split2(a[2] + sfb[ch0], a[3] + sfb[ch0 + 1], h2, l2);
                *(u32*)(smem + OFF_TH + o1) = h2;
                *(u32*)(smem + OFF_TL + o1) = l2;
            }
    }
    __syncthreads();

    // ---- phase 3: ctx = sum_l gates[l]*x_list[l] -> AH/AL ----
    {
        const float* b0 = xl + ((size_t)(0 * Nn + n) * CCH) * HWSZ + hw0;
        const float* b1 = xl + ((size_t)(1 * Nn + n) * CCH) * HWSZ + hw0;
        const float* b2 = xl + ((size_t)(2 * Nn + n) * CCH) * HWSZ + hw0;
        float4 g0 = *(const float4*)(gsf + 0 * 128 + 4 * p4);
        float4 g1 = *(const float4*)(gsf + 1 * 128 + 4 * p4);
        float4 g2 = *(const float4*)(gsf + 2 * 128 + 4 * p4);
        float g0v[4] = {g0.x, g0.y, g0.z, g0.w};
        float g1v[4] = {g1.x, g1.y, g1.z, g1.w};
        float g2v[4] = {g2.x, g2.y, g2.z, g2.w};
        #pragma unroll 2
        for (int i = 0; i < 12; ++i) {
            int c = 2 * c2b + 16 * i;
            size_t oa = (size_t)c * HWSZ + 4 * p4;
            size_t ob = oa + HWSZ;
            float4 a0 = *(const float4*)(b0 + oa), a1 = *(const float4*)(b1 + oa), a2 = *(const float4*)(b2 + oa);
            float4 c0 = *(const float4*)(b0 + ob), c1 = *(const float4*)(b1 + ob), c2 = *(const float4*)(b2 + ob);
            float a0v[4] = {a0.x, a0.y, a0.z, a0.w};
            float a1v[4] = {a1.x, a1.y, a1.z, a1.w};
            float a2v[4] = {a2.x, a2.y, a2.z, a2.w};
            float c0v[4] = {c0.x, c0.y, c0.z, c0.w};
            float c1v[4] = {c1.x, c1.y, c1.z, c1.w};
            float c2v[4] = {c2.x, c2.y, c2.z, c2.w};
            #pragma unroll
            for (int j = 0; j < 4; ++j) {
                float va = fmaf(g2v[j], a2v[j], fmaf(g1v[j], a1v[j], g0v[j] * a0v[j]));
                float vb = fmaf(g2v[j], c2v[j], fmaf(g1v[j], c1v[j], g0v[j] * c0v[j]));
                u32 h2, l2;
                split2(va, vb, h2, l2);
                u32 px = (u32)(4 * p4 + j);
                u32 off = px * 384u + (((u32)(2 * c)) ^ ((px & 7u) << 4));
                *(u32*)(smem + OFF_AH + off) = h2;
                *(u32*)(smem + OFF_AL + off) = l2;
            }
        }
    }

    // ---- GEMM2: mod = ctx @ hw ; t = q*(mod+hb) -> TH/TL in place ----
    #pragma unroll 1
    for (int c = 0; c < 3; ++c) {
        float acc[32];
        #pragma unroll
        for (int m = 0; m < 32; ++m) acc[m] = 0.f;
        stage_w(smem, ph, 6 + 2 * c + 1, t);
        gemm_half(smb, OFF_AH, OFF_AL, 0u, acc, wm, wn, lane);
        stage_w(smem, ph, 6 + 2 * c + 2, t);
        gemm_half(smb, OFF_AH, OFF_AL, 192u, acc, wm, wn, lane);
        #pragma unroll
        for (int mt = 0; mt < 2; ++mt)
            #pragma unroll
            for (int nt = 0; nt < 4; ++nt) {
                int ch0 = 64 * c + 32 * wn + 8 * nt + 2 * tq;
                int r0 = 32 * wm + 16 * mt + gg;
                const float* a = &acc[mt * 16 + nt * 4];
                u32 sw = (((u32)(2 * ch0)) ^ (((u32)r0 & 7u) << 4));
                u32 o0 = (u32)r0 * 384u + sw;
                u32 o1 = o0 + 8u * 384u;
                u32 qh = *(u32*)(smem + OFF_TH + o0);
                u32 ql = *(u32*)(smem + OFF_TL + o0);
                float q0 = __uint_as_float(qh << 16) + __uint_as_float(ql << 16);
                float q1 = __uint_as_float(qh & 0xFFFF0000u) + __uint_as_float(ql & 0xFFFF0000u);
                float t0 = q0 * (a[0] + shb[ch0]);
                float t1 = q1 * (a[1] + shb[ch0 + 1]);
                u32 h2, l2;
                split2(t0, t1, h2, l2);
                *(u32*)(smem + OFF_TH + o0) = h2;
                *(u32*)(smem + OFF_TL + o0) = l2;
                qh = *(u32*)(smem + OFF_TH + o1);
                ql = *(u32*)(smem + OFF_TL + o1);
                q0 = __uint_as_float(qh << 16) + __uint_as_float(ql << 16);
                q1 = __uint_as_float(qh & 0xFFFF0000u) + __uint_as_float(ql & 0xFFFF0000u);
                t0 = q0 * (a[2] + shb[ch0]);
                t1 = q1 * (a[3] + shb[ch0 + 1]);
                split2(t0, t1, h2, l2);
                *(u32*)(smem + OFF_TH + o1) = h2;
                *(u32*)(smem + OFF_TL + o1) = l2;
            }
    }

    // ---- GEMM3: y = t @ pw ; y+pb -> py fp32 [ch][128px] (overlays A) ----
    #pragma unroll 1
    for (int c = 0; c < 3; ++c) {
        float acc[32];
        #pragma unroll
        for (int m = 0; m < 32; ++m) acc[m] = 0.f;
        stage_w(smem, ph, 12 + 2 * c + 1, t);
        gemm_half(smb, OFF_TH, OFF_TL, 0u, acc, wm, wn, lane);
        stage_w(smem, ph, 12 + 2 * c + 2, t);
        gemm_half(smb, OFF_TH, OFF_TL, 192u, acc, wm, wn, lane);
        #pragma unroll
        for (int mt = 0; mt < 2; ++mt)
            #pragma unroll
            for (int nt = 0; nt < 4; ++nt) {
                int ch0 = 64 * c + 32 * wn + 8 * nt + 2 * tq;
                int r0 = 32 * wm + 16 * mt + gg;
                int r1 = r0 + 8;
                const float* a = &acc[mt * 16 + nt * 4];
                u32 s0 = (u32)ch0 * 512u + (((u32)(4 * r0)) ^ (((u32)ch0 & 7u) << 4));
                u32 s1 = (u32)(ch0 + 1) * 512u + (((u32)(4 * r0)) ^ (((u32)(ch0 + 1) & 7u) << 4));
                u32 s2 = (u32)ch0 * 512u + (((u32)(4 * r1)) ^ (((u32)ch0 & 7u) << 4));
                u32 s3 = (u32)(ch0 + 1) * 512u + (((u32)(4 * r1)) ^ (((u32)(ch0 + 1) & 7u) << 4));
                *(float*)(smem + s0) = a[0] + spb[ch0];
                *(float*)(smem + s1) = a[1] + spb[ch0 + 1];
                *(float*)(smem + s2) = a[2] + spb[ch0];
                *(float*)(smem + s3) = a[3] + spb[ch0 + 1];
            }
    }
    __syncthreads();

    // ---- phase 6: LN stats over py ----
    float* ps  = (float*)(smem + OFF_W);
    float* qs  = ps + 256;
    float* mus = ps + 512;
    float* rss = ps + 640;
    {
        int px = t & 127, half = t >> 7;
        float s = 0.f, s2 = 0.f;
        #pragma unroll 4
        for (int ch = 96 * half; ch < 96 * half + 96; ++ch) {
            float v = *(float*)(smem + (u32)ch * 512u + (((u32)(4 * px)) ^ (((u32)ch & 7u) << 4)));
            s += v;
            s2 = fmaf(v, v, s2);
        }
        ps[t] = s; qs[t] = s2;
    }
    __syncthreads();
    if (t < 128) {
        float st = ps[t] + ps[t + 128];
        float qt = qs[t] + qs[t + 128];
        float mu  = st * (1.0f / CCH);
        float var = qt * (1.0f / CCH) - mu * mu;
        mus[t] = mu;
        rss[t] = rsqrtf(var + EPSV);
    }
    __syncthreads();

    // ---- phase 7: normalize + residual + coalesced store ----
    {
        const float* xb = x + ((size_t)n * CCH) * HWSZ + hw0;
        float* ob = out + ((size_t)n * CCH) * HWSZ + hw0;
        #pragma unroll 4
        for (int u = 0; u < 24; ++u) {
            int f4 = t + 256 * u;
            int c = f4 >> 5, L = f4 & 31;
            float4 y = *(const float4*)(smem + (u32)c * 512u + (((u32)(16 * L)) ^ (((u32)c & 7u) << 4)));
            float4 xv = *(const float4*)(xb + (size_t)c * HWSZ + 4 * L);
            float4 m = *(const float4*)(mus + 4 * L);
            float4 r = *(const float4*)(rss + 4 * L);
            float lw = slw[c], lb = slb[c];
            float4 o;
            o.x = fmaf(lw * (y.x - m.x), r.x, lb) + xv.x;
            o.y = fmaf(lw * (y.y - m.y), r.y, lb) + xv.y;
            o.z = fmaf(lw * (y.z - m.z), r.z, lb) + xv.z;
            o.w = fmaf(lw * (y.w - m.w), r.w, lb) + xv.w;
            *(float4*)(ob + (size_t)c * HWSZ + 4 * L) = o;
        }
    }
}

extern "C" void kernel_launch(void* const* d_in, const int* in_sizes, int n_in,
                              void* d_out, int out_size) {
    const float* x   = (const float*)d_in[0];
    const float* xl  = (const float*)d_in[1];
    const float* fw  = (const float*)d_in[2];
    const float* fb  = (const float*)d_in[3];
    const float* hwm = (const float*)d_in[4];
    const float* hb  = (const float*)d_in[5];
    const float* pw  = (const float*)d_in[6];
    const float* pb  = (const float*)d_in[7];
    const float* lnw = (const float*)d_in[8];
    const float* lnb = (const float*)d_in[9];
    float* out = (float*)d_out;

    int Nn = in_sizes[0] / (CCH * HWSZ);

    CM_wconv_kernel<<<(3 * 192 * 192 + 255) / 256, 256>>>(fw, hwm, pw);

    cudaFuncSetAttribute(CM_29540785062535_kernel,
                         cudaFuncAttributeMaxDynamicSharedMemorySize, SMEM_TOTAL);

    int blocks = Nn * (HWSZ / 128);   // 2048
    CM_29540785062535_kernel<<<blocks, NTHR, SMEM_TOTAL>>>(
        x, xl, fw, fb, hb, pb, lnw, lnb, out, Nn);
}

// round 10
// speedup vs baseline: 2.5449x; 1.0959x over previous
#include <cuda_runtime.h>

typedef unsigned int u32;
typedef unsigned short u16;

#define CCH  192
#define HWSZ 16384
#define NTHR 384
#define EPSV 1e-6f

// ---- smem byte offsets ----
#define OFF_AH 0u          // A hi: 128px x 192ch bf16, 384B/row, XOR16 swizzle
#define OFF_AL 49152u      // A lo
#define OFF_TH 98304u      // T (q then t) hi   (gate partials overlay early)
#define OFF_TL 147456u     // T lo
#define OFF_W  196608u     // weight quarter: 96n x (48k hi |pad| 48k lo) 256B/row = 24576B
#define OFF_GS 221184u     // gates 3x128 f32
#define OFF_FB 222720u     // fb 196 f32
#define OFF_HB 223504u
#define OFF_PB 224272u
#define OFF_LW 225040u
#define OFF_LB 225808u
#define OFF_MU 226576u     // 128 f32
#define OFF_RS 227088u     // 128 f32
#define SMEM_TOTAL 227600
// py (fp32 y, [ch][128px] stride 512B, swizzled) overlays OFF_AH..98304
// LN partials overlay OFF_W

// pre-converted weights: 24 regions = 3 gemms x 2 chunks(96n) x 4 k-quarters(48k),
// each 96 rows x 256B (48k hi | pad | 48k lo), pre-swizzled. 589824 B.
__device__ __align__(16) u16 g_wc[294912];

__device__ __forceinline__ u32 cvt2(float lo, float hi) {
    u32 r; asm("cvt.rn.bf16x2.f32 %0, %1, %2;" : "=r"(r) : "f"(hi), "f"(lo)); return r;
}
__device__ __forceinline__ void split2(float a, float b, u32& h2, u32& l2) {
    h2 = cvt2(a, b);
    float ah = __uint_as_float(h2 << 16);
    float bh = __uint_as_float(h2 & 0xFFFF0000u);
    l2 = cvt2(a - ah, b - bh);
}
__device__ __forceinline__ u32 smem_u32_of(const void* p) {
    u32 a;
    asm("{ .reg .u64 t; cvta.to.shared.u64 t, %1; cvt.u32.u64 %0, t; }" : "=r"(a) : "l"(p));
    return a;
}
__device__ __forceinline__ void ldsm4(u32& r0, u32& r1, u32& r2, u32& r3, u32 a) {
    asm volatile("ldmatrix.sync.aligned.m8n8.x4.shared.b16 {%0,%1,%2,%3}, [%4];"
                 : "=r"(r0), "=r"(r1), "=r"(r2), "=r"(r3) : "r"(a));
}
__device__ __forceinline__ void mma16816(float* d, u32 a0, u32 a1, u32 a2, u32 a3,
                                         u32 b0, u32 b1) {
    asm volatile(
        "mma.sync.aligned.m16n8k16.row.col.f32.bf16.bf16.f32 "
        "{%0,%1,%2,%3}, {%4,%5,%6,%7}, {%8,%9}, {%0,%1,%2,%3};"
        : "+f"(d[0]), "+f"(d[1]), "+f"(d[2]), "+f"(d[3])
        : "r"(a0), "r"(a1), "r"(a2), "r"(a3), "r"(b0), "r"(b1));
}

// ---- pre-kernel: fp32 weights -> bf16 hi/lo, 24-region quarter layout ----
__global__ void CM_wconv_kernel(const float* __restrict__ fw,
                                const float* __restrict__ hwm,
                                const float* __restrict__ pw) {
    int idx = blockIdx.x * 256 + threadIdx.x;
    if (idx >= 3 * 192 * 192) return;
    int g = idx / (192 * 192);
    int rem = idx - g * (192 * 192);
    int r = rem / 192, k = rem - (rem / 192) * 192;
    const float* src = (g == 0) ? fw : (g == 1) ? hwm : pw;
    float w = src[r * 192 + k];
    u32 h2 = cvt2(w, 0.f);
    float hf = __uint_as_float(h2 << 16);
    u32 l2 = cvt2(w - hf, 0.f);
    int region = g * 8 + (r / 96) * 4 + (k / 48);
    int rr = r % 96, kk = k % 48;
    u32 base = (u32)region * 24576u + (u32)rr * 256u;
    u32 sw = ((u32)rr & 7u) << 4;
    g_wc[(base + (((u32)(2 * kk)) ^ sw)) >> 1]        = (u16)(h2 & 0xFFFFu);
    g_wc[(base + 128u + (((u32)(2 * kk)) ^ sw)) >> 1] = (u16)(l2 & 0xFFFFu);
}

// stage one 24576B weight region from ph regs -> smem, prefetch region nidx
__device__ __forceinline__ void stage_w(char* smem, uint4 (&ph)[4], int nidx, int t) {
    __syncthreads();
    #pragma unroll
    for (int j = 0; j < 4; ++j) ((uint4*)(smem + OFF_W))[t + 384 * j] = ph[j];
    __syncthreads();
    if (nidx < 24) {
        const uint4* gw = (const uint4*)g_wc;
        #pragma unroll
        for (int j = 0; j < 4; ++j) ph[j] = gw[(size_t)nidx * 1536 + t + 384 * j];
    }
}

// one K-quarter: 3 k-steps, Mt=2 x Nt=4 warp tile, 3 split-products
__device__ __forceinline__ void gemm_quarter(u32 smb, u32 offH, u32 offL, u32 kbyte,
                                             float (&acc)[32], int wm, int wn, int lane) {
    const u32 aswz = (u32)(lane & 7) << 4;
    const u32 arow = 32u * (u32)wm + (u32)(lane & 7) + ((u32)(lane >> 3) & 1u) * 8u;
    const u32 abh  = smb + offH + arow * 384u;
    const u32 abl  = smb + offL + arow * 384u;
    const u32 axor = ((u32)(lane >> 4) & 1u) * 16u;
    const u32 brow = 32u * (u32)wn + (u32)(lane & 7);
    const u32 bb   = smb + OFF_W + brow * 256u;
    const u32 bcol0 = ((u32)(lane >> 4) & 1u) * 128u + ((u32)(lane >> 3) & 1u) * 16u;
    #pragma unroll
    for (int ks = 0; ks < 3; ++ks) {
        u32 acol = (kbyte + 32u * (u32)ks + axor) ^ aswz;
        u32 fa[16];
        ldsm4(fa[0],  fa[1],  fa[2],  fa[3],  abh + acol);
        ldsm4(fa[4],  fa[5],  fa[6],  fa[7],  abl + acol);
        ldsm4(fa[8],  fa[9],  fa[10], fa[11], abh + 6144u + acol);
        ldsm4(fa[12], fa[13], fa[14], fa[15], abl + 6144u + acol);
        u32 bcol = (bcol0 + 32u * (u32)ks) ^ aswz;
        u32 fb[16];
        ldsm4(fb[0],  fb[1],  fb[2],  fb[3],  bb + bcol);
        ldsm4(fb[4],  fb[5],  fb[6],  fb[7],  bb + 2048u + bcol);
        ldsm4(fb[8],  fb[9],  fb[10], fb[11], bb + 4096u + bcol);
        ldsm4(fb[12], fb[13], fb[14], fb[15], bb + 6144u + bcol);
        #pragma unroll
        for (int mt = 0; mt < 2; ++mt)
            #pragma unroll
            for (int nt = 0; nt < 4; ++nt) {
                float* a = &acc[mt * 16 + nt * 4];
                mma16816(a, fa[8*mt+0], fa[8*mt+1], fa[8*mt+2], fa[8*mt+3],
                         fb[4*nt+0], fb[4*nt+1]);                          // hh
                mma16816(a, fa[8*mt+0], fa[8*mt+1], fa[8*mt+2], fa[8*mt+3],
                         fb[4*nt+2], fb[4*nt+3]);                          // h*lo(B)
                mma16816(a, fa[8*mt+4], fa[8*mt+5], fa[8*mt+6], fa[8*mt+7],
                         fb[4*nt+0], fb[4*nt+1]);                          // lo(A)*h
            }
    }
}

__global__ void __launch_bounds__(NTHR)
CM_29540785062535_kernel(const float* __restrict__ x,
                         const float* __restrict__ xl,
                         const float* __restrict__ fw,
                         const float* __restrict__ fbg,
                         const float* __restrict__ hbg,
                         const float* __restrict__ pbg,
                         const float* __restrict__ lnwg,
                         const float* __restrict__ lnbg,
                         float* __restrict__ out,
                         int Nn)
{
    extern __shared__ char smem[];
    const u32 smb = smem_u32_of(smem);
    const int t    = threadIdx.x;
    const int lane = t & 31;
    const int w    = t >> 5;
    const int wm   = w & 3;        // 4 M positions (32px each)
    const int wn   = w >> 2;       // 3 N positions (32ch within 96-chunk)

    const int n   = blockIdx.x >> 7;
    const int hw0 = (blockIdx.x & 127) << 7;

    float* sfb = (float*)(smem + OFF_FB);
    float* shb = (float*)(smem + OFF_HB);
    float* spb = (float*)(smem + OFF_PB);
    float* slw = (float*)(smem + OFF_LW);
    float* slb = (float*)(smem + OFF_LB);
    float* gsf = (float*)(smem + OFF_GS);
    float* mus = (float*)(smem + OFF_MU);
    float* rss = (float*)(smem + OFF_RS);

    for (int i = t; i < 195; i += NTHR) sfb[i] = fbg[i];
    for (int i = t; i < 192; i += NTHR) {
        shb[i] = hbg[i]; spb[i] = pbg[i]; slw[i] = lnwg[i]; slb[i] = lnbg[i];
    }

    const int px4 = t & 31;        // pixel quad (constant per thread)
    const int cpb = t >> 5;        // channel-pair group base (0..11)

    // ---- phase 1: stage x -> AH/AL + gate partials (gpart overlays TH) ----
    {
        const float* xb = x + ((size_t)n * CCH) * HWSZ + hw0;
        float* gpart = (float*)(smem + OFF_TH);
        float ga[12];
        #pragma unroll
        for (int m = 0; m < 12; ++m) ga[m] = 0.f;
        #pragma unroll 2
        for (int j = 0; j < 8; ++j) {
            int cp = cpb + 12 * j;           // 0..95
            int c = 2 * cp;
            float4 a = *(const float4*)(xb + (size_t)c * HWSZ + 4 * px4);
            float4 b = *(const float4*)(xb + (size_t)(c + 1) * HWSZ + 4 * px4);
            float av[4] = {a.x, a.y, a.z, a.w};
            float bv[4] = {b.x, b.y, b.z, b.w};
            #pragma unroll
            for (int jj = 0; jj < 4; ++jj) {
                u32 h2, l2;
                split2(av[jj], bv[jj], h2, l2);
                u32 px = (u32)(4 * px4 + jj);
                u32 off = px * 384u + (((u32)(2 * c)) ^ ((px & 7u) << 4));
                *(u32*)(smem + OFF_AH + off) = h2;
                *(u32*)(smem + OFF_AL + off) = l2;
            }
            #pragma unroll
            for (int l = 0; l < 3; ++l) {
                float w0 = __ldg(fw + (size_t)(192 + l) * 192 + c);
                float w1 = __ldg(fw + (size_t)(192 + l) * 192 + c + 1);
                #pragma unroll
                for (int jj = 0; jj < 4; ++jj)
                    ga[l * 4 + jj] = fmaf(w0, av[jj], fmaf(w1, bv[jj], ga[l * 4 + jj]));
            }
        }
        #pragma unroll
        for (int l = 0; l < 3; ++l)
            #pragma unroll
            for (int jj = 0; jj < 4; ++jj)
                gpart[cpb * 384 + l * 128 + 4 * px4 + jj] = ga[l * 4 + jj];
    }
    __syncthreads();
    // gate reduction: one (l, px) slot per thread
    {
        const float* gpart = (const float*)(smem + OFF_TH);
        float v = sfb[192 + (t >> 7)];
        #pragma unroll
        for (int g = 0; g < 12; ++g) v += gpart[g * 384 + t];
        gsf[t] = v;
    }
    __syncthreads();

    const int tq = lane & 3;
    const int gg = lane >> 2;

    uint4 ph[4];
    {
        const uint4* gw = (const uint4*)g_wc;
        #pragma unroll
        for (int j = 0; j < 4; ++j) ph[j] = gw[t + 384 * j];   // region 0
    }
    int reg = 0;

    // ---- GEMM1: q = x @ fw ; q+fb -> TH/TL ----
    #pragma unroll 1
    for (int ci = 0; ci < 2; ++ci) {
        float acc[32];
        #pragma unroll
        for (int m = 0; m < 32; ++m) acc[m] = 0.f;
        #pragma unroll 1
        for (int qk = 0; qk < 4; ++qk) {
            stage_w(smem, ph, reg + 1, t);
            gemm_quarter(smb, OFF_AH, OFF_AL, 96u * (u32)qk, acc, wm, wn, lane);
            ++reg;
        }
        #pragma unroll
        for (int mt = 0; mt < 2; ++mt)
            #pragma unroll
            for (int nt = 0; nt < 4; ++nt) {
                int ch0 = 96 * ci + 32 * wn + 8 * nt + 2 * tq;
                int r0 = 32 * wm + 16 * mt + gg;
                const float* a = &acc[mt * 16 + nt * 4];
                u32 o0 = (u32)r0 * 384u + (((u32)(2 * ch0)) ^ (((u32)r0 & 7u) << 4));
                u32 o1 = o0 + 8u * 384u;
                u32 h2, l2;
                split2(a[0] + sfb[ch0], a[1] + sfb[ch0 + 1], h2, l2);
                *(u32*)(smem + OFF_TH + o0) = h2;
                *(u32*)(smem + OFF_TL + o0) = l2;
                split2(a[2] + sfb[ch0], a[3] + sfb[ch0 + 1], h2, l2);
                *(u32*)(smem + OFF_TH + o1) = h2;
                *(u32*)(smem + OFF_TL + o1) = l2;
            }
    }
    __syncthreads();   // all warps done reading A before ctx overwrites it

    // ---- phase 3: ctx = sum_l gates[l]*x_list[l] -> AH/AL ----
    {
        const float* b0 = xl + ((size_t)(0 * Nn + n) * CCH) * HWSZ + hw0;
        const float* b1 = xl + ((size_t)(1 * Nn + n) * CCH) * HWSZ + hw0;
        const float* b2 = xl + ((size_t)(2 * Nn + n) * CCH) * HWSZ + hw0;
        float4 g0 = *(const float4*)(gsf + 0 * 128 + 4 * px4);
        float4 g1 = *(const float4*)(gsf + 1 * 128 + 4 * px4);
        float4 g2 = *(const float4*)(gsf + 2 * 128 + 4 * px4);
        float g0v[4] = {g0.x, g0.y, g0.z, g0.w};
        float g1v[4] = {g1.x, g1.y, g1.z, g1.w};
        float g2v[4] = {g2.x, g2.y, g2.z, g2.w};
        #pragma unroll 2
        for (int j = 0; j < 8; ++j) {
            int cp = cpb + 12 * j;
            int c = 2 * cp;
            size_t oa = (size_t)c * HWSZ + 4 * px4;
            size_t ob = oa + HWSZ;
            float4 a0 = *(const float4*)(b0 + oa), a1 = *(const float4*)(b1 + oa), a2 = *(const float4*)(b2 + oa);
            float4 c0 = *(const float4*)(b0 + ob), c1 = *(const float4*)(b1 + ob), c2 = *(const float4*)(b2 + ob);
            float a0v[4] = {a0.x, a0.y, a0.z, a0.w};
            float a1v[4] = {a1.x, a1.y, a1.z, a1.w};
            float a2v[4] = {a2.x, a2.y, a2.z, a2.w};
            float c0v[4] = {c0.x, c0.y, c0.z, c0.w};
            float c1v[4] = {c1.x, c1.y, c1.z, c1.w};
            float c2v[4] = {c2.x, c2.y, c2.z, c2.w};
            #pragma unroll
            for (int jj = 0; jj < 4; ++jj) {
                float va = fmaf(g2v[jj], a2v[jj], fmaf(g1v[jj], a1v[jj], g0v[jj] * a0v[jj]));
                float vb = fmaf(g2v[jj], c2v[jj], fmaf(g1v[jj], c1v[jj], g0v[jj] * c0v[jj]));
                u32 h2, l2;
                split2(va, vb, h2, l2);
                u32 px = (u32)(4 * px4 + jj);
                u32 off = px * 384u + (((u32)(2 * c)) ^ ((px & 7u) << 4));
                *(u32*)(smem + OFF_AH + off) = h2;
                *(u32*)(smem + OFF_AL + off) = l2;
            }
        }
    }

    // ---- GEMM2: mod = ctx @ hw ; t = q*(mod+hb) -> TH/TL in place ----
    #pragma unroll 1
    for (int ci = 0; ci < 2; ++ci) {
        float acc[32];
        #pragma unroll
        for (int m = 0; m < 32; ++m) acc[m] = 0.f;
        #pragma unroll 1
        for (int qk = 0; qk < 4; ++qk) {
            stage_w(smem, ph, reg + 1, t);
            gemm_quarter(smb, OFF_AH, OFF_AL, 96u * (u32)qk, acc, wm, wn, lane);
            ++reg;
        }
        #pragma unroll
        for (int mt = 0; mt < 2; ++mt)
            #pragma unroll
            for (int nt = 0; nt < 4; ++nt) {
                int ch0 = 96 * ci + 32 * wn + 8 * nt + 2 * tq;
                int r0 = 32 * wm + 16 * mt + gg;
                const float* a = &acc[mt * 16 + nt * 4];
                u32 o0 = (u32)r0 * 384u + (((u32)(2 * ch0)) ^ (((u32)r0 & 7u) << 4));
                u32 o1 = o0 + 8u * 384u;
                u32 qh = *(u32*)(smem + OFF_TH + o0);
                u32 ql = *(u32*)(smem + OFF_TL + o0);
                float q0 = __uint_as_float(qh << 16) + __uint_as_float(ql << 16);
                float q1 = __uint_as_float(qh & 0xFFFF0000u) + __uint_as_float(ql & 0xFFFF0000u);
                float t0 = q0 * (a[0] + shb[ch0]);
                float t1 = q1 * (a[1] + shb[ch0 + 1]);
                u32 h2, l2;
                split2(t0, t1, h2, l2);
                *(u32*)(smem + OFF_TH + o0) = h2;
                *(u32*)(smem + OFF_TL + o0) = l2;
                qh = *(u32*)(smem + OFF_TH + o1);
                ql = *(u32*)(smem + OFF_TL + o1);
                q0 = __uint_as_float(qh << 16) + __uint_as_float(ql << 16);
                q1 = __uint_as_float(qh & 0xFFFF0000u) + __uint_as_float(ql & 0xFFFF0000u);
                t0 = q0 * (a[2] + shb[ch0]);
                t1 = q1 * (a[3] + shb[ch0 + 1]);
                split2(t0, t1, h2, l2);
                *(u32*)(smem + OFF_TH + o1) = h2;
                *(u32*)(smem + OFF_TL + o1) = l2;
            }
    }

    // ---- GEMM3: y = t @ pw ; y+pb -> py fp32 [ch][128px] (overlays A) ----
    #pragma unroll 1
    for (int ci = 0; ci < 2; ++ci) {
        float acc[32];
        #pragma unroll
        for (int m = 0; m < 32; ++m) acc[m] = 0.f;
        #pragma unroll 1
        for (int qk = 0; qk < 4; ++qk) {
            stage_w(smem, ph, reg + 1, t);
            gemm_quarter(smb, OFF_TH, OFF_TL, 96u * (u32)qk, acc, wm, wn, lane);
            ++reg;
        }
        #pragma unroll
        for (int mt = 0; mt < 2; ++mt)
            #pragma unroll
            for (int nt = 0; nt < 4; ++nt) {
                int ch0 = 96 * ci + 32 * wn + 8 * nt + 2 * tq;
                int r0 = 32 * wm + 16 * mt + gg;
                int r1 = r0 + 8;
                const float* a = &acc[mt * 16 + nt * 4];
                u32 s0 = (u32)ch0 * 512u + (((u32)(4 * r0)) ^ (((u32)ch0 & 7u) << 4));
                u32 s1 = (u32)(ch0 + 1) * 512u + (((u32)(4 * r0)) ^ (((u32)(ch0 + 1) & 7u) << 4));
                u32 s2 = (u32)ch0 * 512u + (((u32)(4 * r1)) ^ (((u32)ch0 & 7u) << 4));
                u32 s3 = (u32)(ch0 + 1) * 512u + (((u32)(4 * r1)) ^ (((u32)(ch0 + 1) & 7u) << 4));
                *(float*)(smem + s0) = a[0] + spb[ch0];
                *(float*)(smem + s1) = a[1] + spb[ch0 + 1];
                *(float*)(smem + s2) = a[2] + spb[ch0];
                *(float*)(smem + s3) = a[3] + spb[ch0 + 1];
            }
    }
    __syncthreads();

    // ---- LN stats: 3 segs x 128 px (partials overlay W) ----
    {
        float* ps = (float*)(smem + OFF_W);
        float* qs = ps + 384;
        int seg = t >> 7, px = t & 127;
        float s = 0.f, s2 = 0.f;
        #pragma unroll 4
        for (int ch = 64 * seg; ch < 64 * seg + 64; ++ch) {
            float v = *(float*)(smem + (u32)ch * 512u + (((u32)(4 * px)) ^ (((u32)ch & 7u) << 4)));
            s += v;
            s2 = fmaf(v, v, s2);
        }
        ps[t] = s; qs[t] = s2;
    }
    __syncthreads();
    if (t < 128) {
        float* ps = (float*)(smem + OFF_W);
        float* qs = ps + 384;
        float st = ps[t] + ps[t + 128] + ps[t + 256];
        float qt = qs[t] + qs[t + 128] + qs[t + 256];
        float mu  = st * (1.0f / CCH);
        float var = qt * (1.0f / CCH) - mu * mu;
        mus[t] = mu;
        rss[t] = rsqrtf(var + EPSV);
    }
    __syncthreads();

    // ---- normalize + residual + coalesced store ----
    {
        const float* xb = x + ((size_t)n * CCH) * HWSZ + hw0;
        float* ob = out + ((size_t)n * CCH) * HWSZ + hw0;
        #pragma unroll 4
        for (int u = 0; u < 16; ++u) {
            int f4 = t + 384 * u;
            int c = f4 >> 5, L = f4 & 31;
            float4 y = *(const float4*)(smem + (u32)c * 512u + (((u32)(16 * L)) ^ (((u32)c & 7u) << 4)));
            float4 xv = *(const float4*)(xb + (size_t)c * HWSZ + 4 * L);
            float4 m = *(const float4*)(mus + 4 * L);
            float4 r = *(const float4*)(rss + 4 * L);
            float lw = slw[c], lb = slb[c];
            float4 o;
            o.x = fmaf(lw * (y.x - m.x), r.x, lb) + xv.x;
            o.y = fmaf(lw * (y.y - m.y), r.y, lb) + xv.y;
            o.z = fmaf(lw * (y.z - m.z), r.z, lb) + xv.z;
            o.w = fmaf(lw * (y.w - m.w), r.w, lb) + xv.w;
            *(float4*)(ob + (size_t)c * HWSZ + 4 * L) = o;
        }
    }
}

extern "C" void kernel_launch(void* const* d_in, const int* in_sizes, int n_in,
                              void* d_out, int out_size) {
    const float* x   = (const float*)d_in[0];
    const float* xl  = (const float*)d_in[1];
    const float* fw  = (const float*)d_in[2];
    const float* fb  = (const float*)d_in[3];
    const float* hwm = (const float*)d_in[4];
    const float* hb  = (const float*)d_in[5];
    const float* pw  = (const float*)d_in[6];
    const float* pb  = (const float*)d_in[7];
    const float* lnw = (const float*)d_in[8];
    const float* lnb = (const float*)d_in[9];
    float* out = (float*)d_out;

    int Nn = in_sizes[0] / (CCH * HWSZ);

    CM_wconv_kernel<<<(3 * 192 * 192 + 255) / 256, 256>>>(fw, hwm, pw);

    cudaFuncSetAttribute(CM_29540785062535_kernel,
                         cudaFuncAttributeMaxDynamicSharedMemorySize, SMEM_TOTAL);

    int blocks = Nn * (HWSZ / 128);   // 2048
    CM_29540785062535_kernel<<<blocks, NTHR, SMEM_TOTAL>>>(
        x, xl, fw, fb, hb, pb, lnw, lnb, out, Nn);
}